// round 1
// baseline (speedup 1.0000x reference)
#include <cuda_runtime.h>
#include <math.h>

// ---------------------------------------------------------------------------
// CapsNet forward, fully fused. One CTA per batch element (grid=128).
// Key identity: routing never needs pred[b,i,o,d].
//   xc[o,c] = sum_i c[o,i] x[c,i]
//   y[o,c'] = sum_c xc[o,c] G[o,c,c'] + C[o]*BW[o,c'],  G = W W^T (per o)
//   |s[o]|^2 = xc.y + C*sB,  sB = BW.xc + C*|B[o]|^2,   v = alpha(o)*s
//   db[o,i]  = alpha[o] * (sum_c' y[o,c'] x[c',i] + sB[o])
// W itself is read only once per layer (final v). G precomputed per launch.
// ---------------------------------------------------------------------------

#define SD 68                  // smem row stride (floats) for 64-wide rows
#define XS_OFF   0
#define BRT_OFF  4352
#define CS_OFF   8704
#define XCS_OFF  13056
#define YS_OFF   17408
#define AUX_OFF  21760
#define WBS_OFF  8704          // conv-weight overlay (over cs/xcs/ys)
#define SMEM_FLOATS 45632
#define SMEM_BYTES (SMEM_FLOATS * 4)

__device__ float g_G1[64 * 64 * 64];
__device__ float g_BW1[64 * 64];
__device__ float g_Bn1[64];
__device__ float g_G2[10 * 64 * 64];
__device__ float g_BW2[10 * 64];
__device__ float g_Bn2[16];

// ---------------------------------------------------------------------------
// Gram precompute: one block per output capsule o (64 for W1, 10 for W2).
// G[o][c][c'] = sum_d W[o*64+d][c] * W[o*64+d][c']
// BW[o][c']   = sum_d B[o*64+d]    * W[o*64+d][c']
// Bn[o]       = sum_d B[o*64+d]^2
// ---------------------------------------------------------------------------
__global__ void gram_kernel(const float* __restrict__ W1, const float* __restrict__ b1,
                            const float* __restrict__ W2, const float* __restrict__ b2)
{
    __shared__ float ws[64 * SD];
    __shared__ float bsv[64];
    int blk = blockIdx.x;
    const float* W;
    const float* bias;
    float* G; float* BW; float* Bn;
    int o;
    if (blk < 64) { o = blk;      W = W1; bias = b1; G = g_G1 + o * 4096; BW = g_BW1 + o * 64; Bn = g_Bn1 + o; }
    else          { o = blk - 64; W = W2; bias = b2; G = g_G2 + o * 4096; BW = g_BW2 + o * 64; Bn = g_Bn2 + o; }
    int tid = threadIdx.x;  // 256 threads

    for (int p = tid; p < 64 * 16; p += 256) {
        int d = p >> 4, q = p & 15;
        float4 v = ((const float4*)(W + (o * 64 + d) * 64))[q];
        ws[d * SD + q * 4 + 0] = v.x;
        ws[d * SD + q * 4 + 1] = v.y;
        ws[d * SD + q * 4 + 2] = v.z;
        ws[d * SD + q * 4 + 3] = v.w;
    }
    if (tid < 64) bsv[tid] = bias[o * 64 + tid];
    __syncthreads();

    for (int p = tid; p < 64 * 16; p += 256) {
        int c = p >> 4, c4 = (p & 15) * 4;
        float a0 = 0.f, a1 = 0.f, a2 = 0.f, a3 = 0.f;
        #pragma unroll 4
        for (int d = 0; d < 64; d++) {
            float wc = ws[d * SD + c];
            a0 += wc * ws[d * SD + c4 + 0];
            a1 += wc * ws[d * SD + c4 + 1];
            a2 += wc * ws[d * SD + c4 + 2];
            a3 += wc * ws[d * SD + c4 + 3];
        }
        G[c * 64 + c4 + 0] = a0;
        G[c * 64 + c4 + 1] = a1;
        G[c * 64 + c4 + 2] = a2;
        G[c * 64 + c4 + 3] = a3;
    }
    if (tid < 64) {
        float acc = 0.f;
        for (int d = 0; d < 64; d++) acc += bsv[d] * ws[d * SD + tid];
        BW[tid] = acc;
    }
    if (tid == 64) {
        float acc = 0.f;
        for (int d = 0; d < 64; d++) acc += bsv[d] * bsv[d];
        *Bn = acc;
    }
}

// ---------------------------------------------------------------------------
// One capsule layer with 3 routing iterations, all state in smem.
// xs (input caps) is [64 c][64 i] with row stride SD. O = 64 or 10.
// ---------------------------------------------------------------------------
__device__ __forceinline__ void cap_layer(
    int O, bool is_final,
    const float* __restrict__ W, const float* __restrict__ bias,
    const float* __restrict__ G, const float* __restrict__ BW, const float* __restrict__ Bn,
    const float* __restrict__ b0, float* __restrict__ outp,
    float* sm, int tid)
{
    float* xs    = sm + XS_OFF;
    float* brt   = sm + BRT_OFF;
    float* cs    = sm + CS_OFF;
    float* xcs   = sm + XCS_OFF;
    float* ys    = sm + YS_OFF;
    float* Cv    = sm + AUX_OFF;
    float* alpha = sm + AUX_OFF + 64;
    float* sB    = sm + AUX_OFF + 128;

    // load routing logits b0 [O][64]
    for (int p = tid; p < O * 64; p += 512)
        brt[(p >> 6) * SD + (p & 63)] = b0[p];
    __syncthreads();

    const int halfO = O >> 1;

    for (int it = 0; it < 3; it++) {
        // ---- softmax over o per input capsule i ----
        if (tid < 64) {
            int i = tid;
            float m = -1e30f;
            for (int o = 0; o < O; o++) m = fmaxf(m, brt[o * SD + i]);
            float ssum = 0.f;
            for (int o = 0; o < O; o++) {
                float e = expf(brt[o * SD + i] - m);
                cs[o * SD + i] = e;
                ssum += e;
            }
            float inv = 1.f / ssum;
            for (int o = 0; o < O; o++) cs[o * SD + i] *= inv;
        }
        __syncthreads();

        // ---- C[o] = sum_i c[o,i] (for bias terms) ----
        if (tid < O) {
            float acc = 0.f;
            const float* cr = cs + tid * SD;
            for (int i = 0; i < 64; i++) acc += cr[i];
            Cv[tid] = acc;
        }

        // ---- xc[o][c] = sum_i c[o,i] * x[c,i]  (2o x 8c register tiles) ----
        for (int t = tid; t < halfO * 8; t += 512) {
            int o0 = (t >> 3) * 2;
            int c8 = (t & 7) * 8;
            float acc0[8], acc1[8];
            #pragma unroll
            for (int j = 0; j < 8; j++) { acc0[j] = 0.f; acc1[j] = 0.f; }
            const float4* ca = (const float4*)(cs + o0 * SD);
            const float4* cb = (const float4*)(cs + (o0 + 1) * SD);
            #pragma unroll 4
            for (int i4 = 0; i4 < 16; i4++) {
                float4 av = ca[i4], bv = cb[i4];
                #pragma unroll
                for (int j = 0; j < 8; j++) {
                    float4 xv = ((const float4*)(xs + (c8 + j) * SD))[i4];
                    acc0[j] += av.x * xv.x + av.y * xv.y + av.z * xv.z + av.w * xv.w;
                    acc1[j] += bv.x * xv.x + bv.y * xv.y + bv.z * xv.z + bv.w * xv.w;
                }
            }
            #pragma unroll
            for (int j = 0; j < 8; j++) {
                xcs[o0 * SD + c8 + j]       = acc0[j];
                xcs[(o0 + 1) * SD + c8 + j] = acc1[j];
            }
        }
        __syncthreads();

        // ---- y[o][c'] = C[o]*BW[o][c'] + sum_c xc[o][c]*G[o][c][c'] (G from L2) ----
        for (int t = tid; t < O * 8; t += 512) {
            int o = t >> 3;
            int c8 = (t & 7) * 8;
            const float* Gp = G + o * 4096 + c8;
            float cf = Cv[o];
            float acc[8];
            #pragma unroll
            for (int j = 0; j < 8; j++) acc[j] = cf * BW[o * 64 + c8 + j];
            const float* xr = xcs + o * SD;
            #pragma unroll 4
            for (int c = 0; c < 64; c++) {
                float xv = xr[c];
                float4 g0 = *(const float4*)(Gp + c * 64);
                float4 g1 = *(const float4*)(Gp + c * 64 + 4);
                acc[0] += xv * g0.x; acc[1] += xv * g0.y;
                acc[2] += xv * g0.z; acc[3] += xv * g0.w;
                acc[4] += xv * g1.x; acc[5] += xv * g1.y;
                acc[6] += xv * g1.z; acc[7] += xv * g1.w;
            }
            #pragma unroll
            for (int j = 0; j < 8; j++) ys[o * SD + c8 + j] = acc[j];
        }
        __syncthreads();

        // ---- |s|^2, alpha (squash scale), bias dot ----
        if (tid < O) {
            int o = tid;
            const float* xr  = xcs + o * SD;
            const float* yr  = ys + o * SD;
            const float* bwr = BW + o * 64;
            float sb = 0.f, nn = 0.f;
            for (int c = 0; c < 64; c++) { sb += bwr[c] * xr[c]; nn += yr[c] * xr[c]; }
            sb += Cv[o] * Bn[o];
            nn += Cv[o] * sb;
            sB[o] = sb;
            alpha[o] = (nn / (1.f + nn)) * rsqrtf(nn + 1e-8f);
        }
        __syncthreads();

        if (it < 2) {
            // ---- b += db;  db[o][i] = alpha[o]*(sum_c y[o,c]*x[c,i] + sB[o]) ----
            for (int t = tid; t < halfO * 8; t += 512) {
                int o0 = (t >> 3) * 2;
                int i8 = (t & 7) * 8;
                float acc0[8], acc1[8];
                #pragma unroll
                for (int j = 0; j < 8; j++) { acc0[j] = 0.f; acc1[j] = 0.f; }
                const float* y0 = ys + o0 * SD;
                const float* y1 = ys + (o0 + 1) * SD;
                #pragma unroll 4
                for (int c = 0; c < 64; c++) {
                    float w0 = y0[c], w1 = y1[c];
                    float4 xa = *(const float4*)(xs + c * SD + i8);
                    float4 xb = *(const float4*)(xs + c * SD + i8 + 4);
                    acc0[0] += w0 * xa.x; acc0[1] += w0 * xa.y;
                    acc0[2] += w0 * xa.z; acc0[3] += w0 * xa.w;
                    acc0[4] += w0 * xb.x; acc0[5] += w0 * xb.y;
                    acc0[6] += w0 * xb.z; acc0[7] += w0 * xb.w;
                    acc1[0] += w1 * xa.x; acc1[1] += w1 * xa.y;
                    acc1[2] += w1 * xa.z; acc1[3] += w1 * xa.w;
                    acc1[4] += w1 * xb.x; acc1[5] += w1 * xb.y;
                    acc1[6] += w1 * xb.z; acc1[7] += w1 * xb.w;
                }
                float a0 = alpha[o0], a1 = alpha[o0 + 1];
                float s0 = sB[o0],    s1 = sB[o0 + 1];
                #pragma unroll
                for (int j = 0; j < 8; j++) {
                    brt[o0 * SD + i8 + j]       += a0 * (acc0[j] + s0);
                    brt[(o0 + 1) * SD + i8 + j] += a1 * (acc1[j] + s1);
                }
            }
            __syncthreads();
        } else {
            // ---- final v[o][d] = alpha[o]*( (W xc)[o,d] + C[o]*B[o,d] ) ----
            for (int t = tid; t < O * 8; t += 512) {
                int o = t >> 3, d8 = (t & 7) * 8;
                float a = alpha[o], cf = Cv[o];
                const float4* xr4 = (const float4*)(xcs + o * SD);
                #pragma unroll
                for (int j = 0; j < 8; j++) {
                    int d = d8 + j;
                    const float4* wr = (const float4*)(W + (o * 64 + d) * 64);
                    float acc = 0.f;
                    #pragma unroll
                    for (int q = 0; q < 16; q++) {
                        float4 wv = wr[q];
                        float4 xv = xr4[q];
                        acc += wv.x * xv.x + wv.y * xv.y + wv.z * xv.z + wv.w * xv.w;
                    }
                    float v = a * (acc + cf * bias[o * 64 + d]);
                    if (is_final) outp[o * 64 + d] = v;
                    else          cs[o * SD + d] = v;   // stage for transpose
                }
            }
            if (!is_final) {
                __syncthreads();
                // x_next[c][i] = v[o=i][d=c]
                for (int p = tid; p < 4096; p += 512) {
                    int c = p >> 6, i = p & 63;
                    xs[c * SD + i] = cs[i * SD + c];
                }
            }
            __syncthreads();
        }
    }
}

// ---------------------------------------------------------------------------
// Main fused kernel: conv3x3 + relu + channel squash, then 3+1 capsule layers.
// ---------------------------------------------------------------------------
__global__ void __launch_bounds__(512, 1)
caps_kernel(const float* __restrict__ gx,  const float* __restrict__ gWb, const float* __restrict__ gbb,
            const float* __restrict__ W1,  const float* __restrict__ b1,
            const float* __restrict__ W2,  const float* __restrict__ b2,
            const float* __restrict__ b_basic, const float* __restrict__ b_cls,
            float* __restrict__ out)
{
    extern __shared__ float sm[];
    int tid = threadIdx.x;
    int b = blockIdx.x;
    float* xs  = sm + XS_OFF;
    float* brt = sm + BRT_OFF;   // conv output buffer before squash
    float* wbs = sm + WBS_OFF;   // conv weights (overlaid on cs/xcs/ys)
    float* fac = sm + AUX_OFF + 128;

    // load x[b] : [64 c][64 i]
    const float* xb = gx + b * 4096;
    for (int p = tid; p < 1024; p += 512) {
        int c = p >> 4, q = p & 15;
        float4 v = ((const float4*)(xb + c * 64))[q];
        xs[c * SD + q * 4 + 0] = v.x;
        xs[c * SD + q * 4 + 1] = v.y;
        xs[c * SD + q * 4 + 2] = v.z;
        xs[c * SD + q * 4 + 3] = v.w;
    }
    // load conv weights [64 co][576], padded stride 577 against bank conflicts
    for (int p = tid; p < 36864; p += 512) {
        int co = p / 576, r = p - co * 576;
        wbs[co * 577 + r] = gWb[p];
    }
    __syncthreads();

    // conv 3x3 SAME: thread = (co, y), computes 8 x-positions
    {
        int co = tid >> 3, y = tid & 7;
        float acc[8];
        float bval = gbb[co];
        #pragma unroll
        for (int j = 0; j < 8; j++) acc[j] = bval;
        const float* wr = wbs + co * 577;
        for (int ci = 0; ci < 64; ci++) {
            const float* xrow = xs + ci * SD;
            const float* wci = wr + ci * 9;
            #pragma unroll
            for (int ky = 0; ky < 3; ky++) {
                int yy = y + ky - 1;
                if (yy >= 0 && yy <= 7) {
                    float rp[10];
                    rp[0] = 0.f; rp[9] = 0.f;
                    #pragma unroll
                    for (int j = 0; j < 8; j++) rp[j + 1] = xrow[yy * 8 + j];
                    #pragma unroll
                    for (int kx = 0; kx < 3; kx++) {
                        float w = wci[ky * 3 + kx];
                        #pragma unroll
                        for (int j = 0; j < 8; j++) acc[j] += w * rp[j + kx];
                    }
                }
            }
        }
        #pragma unroll
        for (int j = 0; j < 8; j++) brt[co * SD + y * 8 + j] = fmaxf(acc[j], 0.f);
    }
    __syncthreads();

    // squash over channels per spatial position
    if (tid < 64) {
        int i = tid;
        float n2 = 0.f;
        for (int c = 0; c < 64; c++) { float h = brt[c * SD + i]; n2 += h * h; }
        fac[i] = (n2 / (1.f + n2)) * rsqrtf(n2 + 1e-8f);
    }
    __syncthreads();
    for (int p = tid; p < 4096; p += 512) {
        int c = p >> 6, i = p & 63;
        xs[c * SD + i] = brt[c * SD + i] * fac[i];
    }
    __syncthreads();

    for (int L = 0; L < 3; L++)
        cap_layer(64, false, W1, b1, g_G1, g_BW1, g_Bn1,
                  b_basic + (size_t)(L * 128 + b) * 4096, nullptr, sm, tid);
    cap_layer(10, true, W2, b2, g_G2, g_BW2, g_Bn2,
              b_cls + (size_t)b * 640, out + (size_t)b * 640, sm, tid);
}

// ---------------------------------------------------------------------------
static const float* pick(void* const* d_in, const int* in_sizes, int n_in, int sz) {
    for (int i = 0; i < n_in; i++)
        if (in_sizes[i] == sz) return (const float*)d_in[i];
    return nullptr;
}

extern "C" void kernel_launch(void* const* d_in, const int* in_sizes, int n_in,
                              void* d_out, int out_size)
{
    // all element counts are distinct -> resolve inputs by size (robust to order)
    const float* x       = pick(d_in, in_sizes, n_in, 128 * 64 * 64);      // 524288
    const float* Wb      = pick(d_in, in_sizes, n_in, 64 * 64 * 9);        // 36864
    const float* bb      = pick(d_in, in_sizes, n_in, 64);                 // 64
    const float* W1      = pick(d_in, in_sizes, n_in, 4096 * 64);          // 262144
    const float* b1      = pick(d_in, in_sizes, n_in, 4096);               // 4096
    const float* W2      = pick(d_in, in_sizes, n_in, 640 * 64);           // 40960
    const float* b2      = pick(d_in, in_sizes, n_in, 640);                // 640
    const float* b_basic = pick(d_in, in_sizes, n_in, 3 * 128 * 64 * 64);  // 1572864
    const float* b_cls   = pick(d_in, in_sizes, n_in, 128 * 10 * 64);      // 81920
    float* out = (float*)d_out;

    cudaFuncSetAttribute(caps_kernel, cudaFuncAttributeMaxDynamicSharedMemorySize, SMEM_BYTES);
    gram_kernel<<<74, 256>>>(W1, b1, W2, b2);
    caps_kernel<<<128, 512, SMEM_BYTES>>>(x, Wb, bb, W1, b1, W2, b2, b_basic, b_cls, out);
}

// round 2
// speedup vs baseline: 1.2131x; 1.2131x over previous
#include <cuda_runtime.h>
#include <cuda_fp16.h>
#include <math.h>

// ---------------------------------------------------------------------------
// CapsNet forward, fully fused. One CTA per batch element (grid=128).
// Routing never materializes pred[b,i,o,d]:
//   xc[o,c] = sum_i c[o,i] x[c,i]
//   y[o,c'] = sum_c xc[o,c] G[o,c,c'] + C[o]*BW[o,c'],  G = W W^T (symmetric)
//   |s|^2   = xc.y + C*sB,  sB = BW.xc + C*|B|^2,  v = alpha*s
//   db[o,i] = alpha[o]*(sum_c y[o,c] x[c,i] + sB[o])
// G stored fp16 (halves L2 traffic); all math fp32.
// Smem GEMMs are outer-product register-tiled: per k-step each warp does
// one float4 broadcast + two coalesced scalar LDS (conflict-free).
// ---------------------------------------------------------------------------

#define SD 68                    // row stride (floats); 68 % 4 == 0 (float4 ok)
#define XS_OFF   0               // xs[c][i]
#define XT_OFF   4352            // xt[i][c]   (conv-out staging too)
#define CT_OFF   8704            // ct[i][o]   softmax coupling coeffs
#define BT_OFF   13056           // bt[i][o]   routing logits
#define XC_OFF   17408           // xc[o][c]
#define YT_OFF   21760           // yt[c][o]
#define AUX_OFF  26112           // Cv[64] | alpha[64] | sB[64] | fac[64]
#define WBS_OFF  8704            // conv weights overlay (conv phase only)
#define SMEM_FLOATS (8704 + 64 * 577)     // 45632
#define SMEM_BYTES  (SMEM_FLOATS * 4)     // 182528

__device__ __align__(16) __half g_G1h[64 * 64 * 64];
__device__ __align__(16) __half g_G2h[10 * 64 * 64];
__device__ float g_BW1[64 * 64];
__device__ float g_Bn1[64];
__device__ float g_BW2[10 * 64];
__device__ float g_Bn2[16];

// ---------------------------------------------------------------------------
// Gram precompute (runs once per launch, 74 blocks):
// G[o][c][c'] = sum_d W[o*64+d][c] * W[o*64+d][c']   (stored fp16)
// BW[o][c']   = sum_d B[o*64+d]    * W[o*64+d][c']
// Bn[o]       = sum_d B[o*64+d]^2
// ---------------------------------------------------------------------------
__global__ void gram_kernel(const float* __restrict__ W1, const float* __restrict__ b1,
                            const float* __restrict__ W2, const float* __restrict__ b2)
{
    __shared__ float ws[64 * SD];
    __shared__ float bsv[64];
    int blk = blockIdx.x;
    const float* W;
    const float* bias;
    __half* G; float* BW; float* Bn;
    int o;
    if (blk < 64) { o = blk;      W = W1; bias = b1; G = g_G1h + o * 4096; BW = g_BW1 + o * 64; Bn = g_Bn1 + o; }
    else          { o = blk - 64; W = W2; bias = b2; G = g_G2h + o * 4096; BW = g_BW2 + o * 64; Bn = g_Bn2 + o; }
    int tid = threadIdx.x;  // 256

    for (int p = tid; p < 64 * 16; p += 256) {
        int d = p >> 4, q = p & 15;
        float4 v = ((const float4*)(W + (o * 64 + d) * 64))[q];
        ws[d * SD + q * 4 + 0] = v.x;
        ws[d * SD + q * 4 + 1] = v.y;
        ws[d * SD + q * 4 + 2] = v.z;
        ws[d * SD + q * 4 + 3] = v.w;
    }
    if (tid < 64) bsv[tid] = bias[o * 64 + tid];
    __syncthreads();

    for (int p = tid; p < 64 * 16; p += 256) {
        int c = p >> 4, c4 = (p & 15) * 4;
        float a0 = 0.f, a1 = 0.f, a2 = 0.f, a3 = 0.f;
        #pragma unroll 4
        for (int d = 0; d < 64; d++) {
            float wc = ws[d * SD + c];
            a0 += wc * ws[d * SD + c4 + 0];
            a1 += wc * ws[d * SD + c4 + 1];
            a2 += wc * ws[d * SD + c4 + 2];
            a3 += wc * ws[d * SD + c4 + 3];
        }
        G[c * 64 + c4 + 0] = __float2half_rn(a0);
        G[c * 64 + c4 + 1] = __float2half_rn(a1);
        G[c * 64 + c4 + 2] = __float2half_rn(a2);
        G[c * 64 + c4 + 3] = __float2half_rn(a3);
    }
    if (tid < 64) {
        float acc = 0.f;
        for (int d = 0; d < 64; d++) acc += bsv[d] * ws[d * SD + tid];
        BW[tid] = acc;
    }
    if (tid == 64) {
        float acc = 0.f;
        for (int d = 0; d < 64; d++) acc += bsv[d] * bsv[d];
        *Bn = acc;
    }
}

// ---------------------------------------------------------------------------
// One capsule layer, 3 routing iterations. x in smem both ways:
//   xs[c][i] (c-major) and xt[i][c] (i-major). O = 64 or 10.
// ---------------------------------------------------------------------------
__device__ __forceinline__ void cap_layer(
    int O, bool is_final,
    const float* __restrict__ W, const float* __restrict__ bias,
    const __half* __restrict__ Gh, const float* __restrict__ BW, const float* __restrict__ Bn,
    const float* __restrict__ b0, float* __restrict__ outp,
    float* sm, int tid)
{
    float* xs = sm + XS_OFF;
    float* xt = sm + XT_OFF;
    float* ct = sm + CT_OFF;
    float* bt = sm + BT_OFF;
    float* xc = sm + XC_OFF;
    float* yt = sm + YT_OFF;
    float* Cv = sm + AUX_OFF;
    float* al = sm + AUX_OFF + 64;
    float* sB = sm + AUX_OFF + 128;

    const int w = tid >> 5, lane = tid & 31;
    const int o0w = w * 4;

    // routing logits, transposed: bt[i][o]
    for (int p = tid; p < O * 64; p += 512)
        bt[(p & 63) * SD + (p >> 6)] = b0[p];
    __syncthreads();

    for (int it = 0; it < 3; it++) {
        // ---- softmax over o, 8 threads per input capsule i ----
        {
            int i = tid >> 3, s = tid & 7;
            int ob = s * 8;
            float v[8];
            float m = -1e30f;
            #pragma unroll
            for (int j = 0; j < 8; j++) {
                int o = ob + j;
                v[j] = (o < O) ? bt[i * SD + o] : -1e30f;
                m = fmaxf(m, v[j]);
            }
            m = fmaxf(m, __shfl_xor_sync(0xffffffffu, m, 1));
            m = fmaxf(m, __shfl_xor_sync(0xffffffffu, m, 2));
            m = fmaxf(m, __shfl_xor_sync(0xffffffffu, m, 4));
            float ssum = 0.f;
            #pragma unroll
            for (int j = 0; j < 8; j++) {
                if (ob + j < O) { v[j] = expf(v[j] - m); ssum += v[j]; }
            }
            ssum += __shfl_xor_sync(0xffffffffu, ssum, 1);
            ssum += __shfl_xor_sync(0xffffffffu, ssum, 2);
            ssum += __shfl_xor_sync(0xffffffffu, ssum, 4);
            float inv = 1.f / ssum;
            #pragma unroll
            for (int j = 0; j < 8; j++)
                if (ob + j < O) ct[i * SD + ob + j] = v[j] * inv;
        }
        __syncthreads();

        // ---- Cv[o] = sum_i c[o,i] (8 threads per o) ----
        {
            int o = tid >> 3, s = tid & 7;
            float a = 0.f;
            if (o < O)
                for (int i = s; i < 64; i += 8) a += ct[i * SD + o];
            a += __shfl_xor_sync(0xffffffffu, a, 1);
            a += __shfl_xor_sync(0xffffffffu, a, 2);
            a += __shfl_xor_sync(0xffffffffu, a, 4);
            if (s == 0 && o < O) Cv[o] = a;
        }

        // ---- xc[o][c] = sum_i ct[i][o] * xt[i][c] ; warp w -> o in [4w,4w+4) ----
        if (o0w < O) {
            float a00 = 0.f, a01 = 0.f, a10 = 0.f, a11 = 0.f;
            float a20 = 0.f, a21 = 0.f, a30 = 0.f, a31 = 0.f;
            #pragma unroll 4
            for (int i = 0; i < 64; i++) {
                float4 cv = *(const float4*)(ct + i * SD + o0w);   // broadcast
                float x0 = xt[i * SD + lane];
                float x1 = xt[i * SD + lane + 32];
                a00 += cv.x * x0; a01 += cv.x * x1;
                a10 += cv.y * x0; a11 += cv.y * x1;
                a20 += cv.z * x0; a21 += cv.z * x1;
                a30 += cv.w * x0; a31 += cv.w * x1;
            }
            if (o0w + 0 < O) { xc[(o0w + 0) * SD + lane] = a00; xc[(o0w + 0) * SD + lane + 32] = a01; }
            if (o0w + 1 < O) { xc[(o0w + 1) * SD + lane] = a10; xc[(o0w + 1) * SD + lane + 32] = a11; }
            if (o0w + 2 < O) { xc[(o0w + 2) * SD + lane] = a20; xc[(o0w + 2) * SD + lane + 32] = a21; }
            if (o0w + 3 < O) { xc[(o0w + 3) * SD + lane] = a30; xc[(o0w + 3) * SD + lane + 32] = a31; }
        }
        __syncthreads();

        // ---- y[o][r] = C*BW[o][r] + sum_c xc[o][c]*G[o][r][c] (G symmetric, fp16)
        //      also |s|^2, sB, alpha via warp reduction. lane -> rows {lane, lane+32}
        if (o0w < O) {
            for (int oo = 0; oo < 4; oo++) {
                int o = o0w + oo;
                if (o >= O) break;
                const __half* Gp = Gh + ((size_t)o << 12);
                const uint4* g0 = (const uint4*)(Gp + (lane << 6));
                const uint4* g1 = (const uint4*)(Gp + ((lane + 32) << 6));
                const float4* xr = (const float4*)(xc + o * SD);
                float cf = Cv[o];
                float bw0 = BW[o * 64 + lane], bw1 = BW[o * 64 + lane + 32];
                float a0 = cf * bw0, a1 = cf * bw1;
                float p0 = 0.f, p1 = 0.f;
                #pragma unroll
                for (int q = 0; q < 8; q++) {
                    uint4 ga = g0[q], gb = g1[q];
                    float4 xA = xr[2 * q], xB = xr[2 * q + 1];
                    float2 t;
                    t = __half22float2(*(__half2*)&ga.x); a0 += t.x * xA.x; p0 += t.y * xA.y;
                    t = __half22float2(*(__half2*)&ga.y); a0 += t.x * xA.z; p0 += t.y * xA.w;
                    t = __half22float2(*(__half2*)&ga.z); a0 += t.x * xB.x; p0 += t.y * xB.y;
                    t = __half22float2(*(__half2*)&ga.w); a0 += t.x * xB.z; p0 += t.y * xB.w;
                    t = __half22float2(*(__half2*)&gb.x); a1 += t.x * xA.x; p1 += t.y * xA.y;
                    t = __half22float2(*(__half2*)&gb.y); a1 += t.x * xA.z; p1 += t.y * xA.w;
                    t = __half22float2(*(__half2*)&gb.z); a1 += t.x * xB.x; p1 += t.y * xB.y;
                    t = __half22float2(*(__half2*)&gb.w); a1 += t.x * xB.z; p1 += t.y * xB.w;
                }
                a0 += p0; a1 += p1;
                yt[lane * SD + o] = a0;
                yt[(lane + 32) * SD + o] = a1;
                float xv0 = xc[o * SD + lane], xv1 = xc[o * SD + lane + 32];
                float nn = a0 * xv0 + a1 * xv1;
                float sb = bw0 * xv0 + bw1 * xv1;
                #pragma unroll
                for (int k = 16; k; k >>= 1) {
                    nn += __shfl_xor_sync(0xffffffffu, nn, k);
                    sb += __shfl_xor_sync(0xffffffffu, sb, k);
                }
                if (lane == 0) {
                    sb += cf * Bn[o];
                    nn += cf * sb;
                    sB[o] = sb;
                    al[o] = (nn / (1.f + nn)) * rsqrtf(nn + 1e-8f);
                }
            }
        }
        __syncthreads();

        if (it < 2) {
            // ---- bt[i][o] += alpha[o]*(sum_c yt[c][o]*xs[c][i] + sB[o]) ----
            if (o0w < O) {
                float a00 = 0.f, a01 = 0.f, a10 = 0.f, a11 = 0.f;
                float a20 = 0.f, a21 = 0.f, a30 = 0.f, a31 = 0.f;
                #pragma unroll 4
                for (int c = 0; c < 64; c++) {
                    float4 yv = *(const float4*)(yt + c * SD + o0w);   // broadcast
                    float x0 = xs[c * SD + lane];
                    float x1 = xs[c * SD + lane + 32];
                    a00 += yv.x * x0; a01 += yv.x * x1;
                    a10 += yv.y * x0; a11 += yv.y * x1;
                    a20 += yv.z * x0; a21 += yv.z * x1;
                    a30 += yv.w * x0; a31 += yv.w * x1;
                }
                #pragma unroll
                for (int j = 0; j < 4; j++) {
                    int o = o0w + j;
                    if (o >= O) break;
                    float av = al[o], sv = sB[o];
                    float r0 = (j == 0) ? a00 : (j == 1) ? a10 : (j == 2) ? a20 : a30;
                    float r1 = (j == 0) ? a01 : (j == 1) ? a11 : (j == 2) ? a21 : a31;
                    bt[lane * SD + o]        += av * (r0 + sv);
                    bt[(lane + 32) * SD + o] += av * (r1 + sv);
                }
            }
            __syncthreads();
        } else {
            // ---- final v[o][d] = alpha[o]*((W xc)[o,d] + C[o]*B[o,d]) ----
            for (int t = tid; t < O * 8; t += 512) {
                int o = t >> 3, d8 = (t & 7) * 8;
                float a = al[o], cf = Cv[o];
                const float4* xr4 = (const float4*)(xc + o * SD);
                #pragma unroll
                for (int j = 0; j < 8; j++) {
                    int d = d8 + j;
                    const float4* wr = (const float4*)(W + (o * 64 + d) * 64);
                    float acc0 = 0.f, acc1 = 0.f;
                    #pragma unroll
                    for (int q = 0; q < 16; q += 2) {
                        float4 w0 = wr[q],     xv0 = xr4[q];
                        float4 w1 = wr[q + 1], xv1 = xr4[q + 1];
                        acc0 += w0.x * xv0.x + w0.y * xv0.y + w0.z * xv0.z + w0.w * xv0.w;
                        acc1 += w1.x * xv1.x + w1.y * xv1.y + w1.z * xv1.z + w1.w * xv1.w;
                    }
                    float v = a * (acc0 + acc1 + cf * bias[o * 64 + d]);
                    if (is_final) outp[o * 64 + d] = v;
                    else          xt[o * SD + d] = v;   // xt_next[i=o][c=d]
                }
            }
            if (!is_final) {
                __syncthreads();
                for (int p = tid; p < 4096; p += 512) {
                    int c = p >> 6, i = p & 63;
                    xs[c * SD + i] = xt[i * SD + c];
                }
            }
            __syncthreads();
        }
    }
}

// ---------------------------------------------------------------------------
// Fused main kernel: conv3x3+relu+channel-squash, then 3+1 capsule layers.
// ---------------------------------------------------------------------------
__global__ void __launch_bounds__(512, 1)
caps_kernel(const float* __restrict__ gx,  const float* __restrict__ gWb, const float* __restrict__ gbb,
            const float* __restrict__ W1,  const float* __restrict__ b1,
            const float* __restrict__ W2,  const float* __restrict__ b2,
            const float* __restrict__ b_basic, const float* __restrict__ b_cls,
            float* __restrict__ out)
{
    extern __shared__ float sm[];
    int tid = threadIdx.x;
    int b = blockIdx.x;
    float* xs    = sm + XS_OFF;
    float* cvout = sm + XT_OFF;     // conv output staging ( == xt region)
    float* xt    = sm + XT_OFF;
    float* wbs   = sm + WBS_OFF;
    float* fac   = sm + AUX_OFF + 192;

    // load x[b]: xs[c][i]
    const float* xb = gx + (size_t)b * 4096;
    for (int p = tid; p < 1024; p += 512) {
        int c = p >> 4, q = p & 15;
        float4 v = ((const float4*)(xb + c * 64))[q];
        xs[c * SD + q * 4 + 0] = v.x;
        xs[c * SD + q * 4 + 1] = v.y;
        xs[c * SD + q * 4 + 2] = v.z;
        xs[c * SD + q * 4 + 3] = v.w;
    }
    // conv weights [64 co][576], stride 577
    for (int p = tid; p < 36864; p += 512) {
        int co = p / 576, r = p - co * 576;
        wbs[co * 577 + r] = gWb[p];
    }
    __syncthreads();

    // conv 3x3 SAME: thread = (co, y), 8 x-positions each
    {
        int co = tid >> 3, y0 = tid & 7;
        float acc[8];
        float bval = gbb[co];
        #pragma unroll
        for (int j = 0; j < 8; j++) acc[j] = bval;
        const float* wr = wbs + co * 577;
        for (int ci = 0; ci < 64; ci++) {
            const float* xrow = xs + ci * SD;
            const float* wci = wr + ci * 9;
            float wreg[9];
            #pragma unroll
            for (int k = 0; k < 9; k++) wreg[k] = wci[k];
            #pragma unroll
            for (int ky = 0; ky < 3; ky++) {
                int yy = y0 + ky - 1;
                if (yy >= 0 && yy <= 7) {
                    float4 r0 = *(const float4*)(xrow + yy * 8);
                    float4 r1 = *(const float4*)(xrow + yy * 8 + 4);
                    float rp[10];
                    rp[0] = 0.f;
                    rp[1] = r0.x; rp[2] = r0.y; rp[3] = r0.z; rp[4] = r0.w;
                    rp[5] = r1.x; rp[6] = r1.y; rp[7] = r1.z; rp[8] = r1.w;
                    rp[9] = 0.f;
                    #pragma unroll
                    for (int kx = 0; kx < 3; kx++) {
                        float wv = wreg[ky * 3 + kx];
                        #pragma unroll
                        for (int j = 0; j < 8; j++) acc[j] += wv * rp[j + kx];
                    }
                }
            }
        }
        #pragma unroll
        for (int j = 0; j < 8; j++) cvout[co * SD + y0 * 8 + j] = fmaxf(acc[j], 0.f);
    }
    __syncthreads();

    // channel squash per spatial position
    if (tid < 64) {
        int i = tid;
        float n2 = 0.f;
        for (int c = 0; c < 64; c++) { float h = cvout[c * SD + i]; n2 += h * h; }
        fac[i] = (n2 / (1.f + n2)) * rsqrtf(n2 + 1e-8f);
    }
    __syncthreads();
    for (int p = tid; p < 4096; p += 512) {
        int c = p >> 6, i = p & 63;
        xs[c * SD + i] = cvout[c * SD + i] * fac[i];
    }
    __syncthreads();
    for (int p = tid; p < 4096; p += 512) {
        int c = p >> 6, i = p & 63;
        xt[i * SD + c] = xs[c * SD + i];     // overwrites cvout (done with it)
    }
    __syncthreads();

    for (int L = 0; L < 3; L++)
        cap_layer(64, false, W1, b1, g_G1h, g_BW1, g_Bn1,
                  b_basic + (size_t)(L * 128 + b) * 4096, nullptr, sm, tid);
    cap_layer(10, true, W2, b2, g_G2h, g_BW2, g_Bn2,
              b_cls + (size_t)b * 640, out + (size_t)b * 640, sm, tid);
}

// ---------------------------------------------------------------------------
static const float* pick(void* const* d_in, const int* in_sizes, int n_in, int sz) {
    for (int i = 0; i < n_in; i++)
        if (in_sizes[i] == sz) return (const float*)d_in[i];
    return nullptr;
}

extern "C" void kernel_launch(void* const* d_in, const int* in_sizes, int n_in,
                              void* d_out, int out_size)
{
    const float* x       = pick(d_in, in_sizes, n_in, 128 * 64 * 64);
    const float* Wb      = pick(d_in, in_sizes, n_in, 64 * 64 * 9);
    const float* bb      = pick(d_in, in_sizes, n_in, 64);
    const float* W1      = pick(d_in, in_sizes, n_in, 4096 * 64);
    const float* b1      = pick(d_in, in_sizes, n_in, 4096);
    const float* W2      = pick(d_in, in_sizes, n_in, 640 * 64);
    const float* b2      = pick(d_in, in_sizes, n_in, 640);
    const float* b_basic = pick(d_in, in_sizes, n_in, 3 * 128 * 64 * 64);
    const float* b_cls   = pick(d_in, in_sizes, n_in, 128 * 10 * 64);
    float* out = (float*)d_out;

    cudaFuncSetAttribute(caps_kernel, cudaFuncAttributeMaxDynamicSharedMemorySize, SMEM_BYTES);
    gram_kernel<<<74, 256>>>(W1, b1, W2, b2);
    caps_kernel<<<128, 512, SMEM_BYTES>>>(x, Wb, bb, W1, b1, W2, b2, b_basic, b_cls, out);
}

// round 3
// speedup vs baseline: 1.9698x; 1.6239x over previous
#include <cuda_runtime.h>
#include <cuda_fp16.h>
#include <math.h>

// ---------------------------------------------------------------------------
// CapsNet forward, fully fused, 1 CTA / batch element, 1024 threads.
// Gram trick: routing never materializes pred.
//   xc[o,c]=sum_i c[o,i]x[c,i];  y[o]=G[o]xc[o]+C*BW[o]  (G=W W^T, fp16)
//   |s|^2=xc.y+C*sB; v=alpha*s;  db[o,i]=alpha*(sum_c y[o,c]x[c,i]+sB)
// All global streams (G, W) read cooperatively: full cache lines per warp
// instruction. All smem scalar arrays use odd stride (65) = conflict-free.
// ---------------------------------------------------------------------------

#define SDX 68                   // stride for float4-read arrays (xs, xc)
#define SDT 65                   // stride for scalar-only arrays
#define SDS 66                   // staging stride

#define XS_OFF   0               // xs[c][i]     64x68
#define XC_OFF   4352            // xc[o][c]     64x68
#define XT_OFF   8704            // xt[i][c]     64x65 (also conv-out staging)
#define CS_OFF   12864           // cs[o][i]     64x65
#define BR_OFF   17024           // br[o][i]     64x65
#define YS_OFF   21184           // ys[o][c]     64x65
#define AUX_OFF  25344           // Cv|al|sB|fac|PM|PS
#define PM_OFF   (AUX_OFF + 256)
#define PS_OFF   (AUX_OFF + 256 + 16 * SDS)
#define WBS_OFF  12864           // conv weights overlay 64x577
#define SMEM_FLOATS (12864 + 64 * 577)    // 49792
#define SMEM_BYTES  (SMEM_FLOATS * 4)     // 199168

__device__ __align__(16) __half g_G1h[64 * 64 * 64];
__device__ __align__(16) __half g_G2h[10 * 64 * 64];
__device__ float g_BW1[64 * 64];
__device__ float g_Bn1[64];
__device__ float g_BW2[10 * 64];
__device__ float g_Bn2[16];

// ---------------------------------------------------------------------------
__global__ void gram_kernel(const float* __restrict__ W1, const float* __restrict__ b1,
                            const float* __restrict__ W2, const float* __restrict__ b2)
{
    __shared__ float ws[64 * SDX];
    __shared__ float bsv[64];
    int blk = blockIdx.x;
    const float* W;
    const float* bias;
    __half* G; float* BW; float* Bn;
    int o;
    if (blk < 64) { o = blk;      W = W1; bias = b1; G = g_G1h + o * 4096; BW = g_BW1 + o * 64; Bn = g_Bn1 + o; }
    else          { o = blk - 64; W = W2; bias = b2; G = g_G2h + o * 4096; BW = g_BW2 + o * 64; Bn = g_Bn2 + o; }
    int tid = threadIdx.x;  // 256

    for (int p = tid; p < 64 * 16; p += 256) {
        int d = p >> 4, q = p & 15;
        float4 v = ((const float4*)(W + (o * 64 + d) * 64))[q];
        ws[d * SDX + q * 4 + 0] = v.x;
        ws[d * SDX + q * 4 + 1] = v.y;
        ws[d * SDX + q * 4 + 2] = v.z;
        ws[d * SDX + q * 4 + 3] = v.w;
    }
    if (tid < 64) bsv[tid] = bias[o * 64 + tid];
    __syncthreads();

    for (int p = tid; p < 64 * 16; p += 256) {
        int c = p >> 4, c4 = (p & 15) * 4;
        float a0 = 0.f, a1 = 0.f, a2 = 0.f, a3 = 0.f;
        #pragma unroll 4
        for (int d = 0; d < 64; d++) {
            float wc = ws[d * SDX + c];
            a0 += wc * ws[d * SDX + c4 + 0];
            a1 += wc * ws[d * SDX + c4 + 1];
            a2 += wc * ws[d * SDX + c4 + 2];
            a3 += wc * ws[d * SDX + c4 + 3];
        }
        G[c * 64 + c4 + 0] = __float2half_rn(a0);
        G[c * 64 + c4 + 1] = __float2half_rn(a1);
        G[c * 64 + c4 + 2] = __float2half_rn(a2);
        G[c * 64 + c4 + 3] = __float2half_rn(a3);
    }
    if (tid < 64) {
        float acc = 0.f;
        for (int d = 0; d < 64; d++) acc += bsv[d] * ws[d * SDX + tid];
        BW[tid] = acc;
    }
    if (tid == 64) {
        float acc = 0.f;
        for (int d = 0; d < 64; d++) acc += bsv[d] * bsv[d];
        *Bn = acc;
    }
}

// ---------------------------------------------------------------------------
// One capsule layer, 3 routing iterations. O = 64 or 10 (even).
// ---------------------------------------------------------------------------
__device__ __forceinline__ void cap_layer(
    int O, bool is_final,
    const float* __restrict__ W, const float* __restrict__ bias,
    const __half* __restrict__ Gh, const float* __restrict__ BW, const float* __restrict__ Bn,
    const float* __restrict__ b0, float* __restrict__ outp,
    float* sm, int tid)
{
    float* xs = sm + XS_OFF;
    float* xc = sm + XC_OFF;
    float* xt = sm + XT_OFF;
    float* cs = sm + CS_OFF;
    float* br = sm + BR_OFF;
    float* ys = sm + YS_OFF;
    float* Cv = sm + AUX_OFF;
    float* al = sm + AUX_OFF + 64;
    float* sB = sm + AUX_OFF + 128;
    float* PM = sm + PM_OFF;
    float* PS = sm + PS_OFF;

    const int w = tid >> 5, lane = tid & 31;
    const int o0 = w * 2;
    const int ii = tid & 63, gg = tid >> 6;        // softmax mapping
    const int ngrp = (O + 3) >> 2;

    // load routing logits br[o][i]
    for (int p = tid; p < O * 64; p += 1024)
        br[(p >> 6) * SDT + (p & 63)] = b0[p];
    __syncthreads();

    for (int it = 0; it < 3; it++) {
        // ---- softmax over o (group gg handles o = 4gg..4gg+3 for input ii) ----
        float ev[4];
        if (gg < ngrp) {
            float m = -1e30f;
            #pragma unroll
            for (int j = 0; j < 4; j++) {
                int o = 4 * gg + j;
                ev[j] = (o < O) ? br[o * SDT + ii] : -1e30f;
                m = fmaxf(m, ev[j]);
            }
            PM[gg * SDS + ii] = m;
        }
        __syncthreads();
        float gmax = -1e30f;
        for (int g2 = 0; g2 < ngrp; g2++) gmax = fmaxf(gmax, PM[g2 * SDS + ii]);
        if (gg < ngrp) {
            float s = 0.f;
            #pragma unroll
            for (int j = 0; j < 4; j++) {
                if (4 * gg + j < O) { ev[j] = __expf(ev[j] - gmax); s += ev[j]; }
                else ev[j] = 0.f;
            }
            PS[gg * SDS + ii] = s;
        }
        __syncthreads();
        float gsum = 0.f;
        for (int g2 = 0; g2 < ngrp; g2++) gsum += PS[g2 * SDS + ii];
        float ginv = 1.f / gsum;
        if (gg < ngrp) {
            #pragma unroll
            for (int j = 0; j < 4; j++)
                if (4 * gg + j < O) cs[(4 * gg + j) * SDT + ii] = ev[j] * ginv;
        }
        __syncthreads();

        // ---- Cv[o] = sum_i c[o,i]; thread (o = tid>>4, s = tid&15) ----
        {
            int o = tid >> 4, s = tid & 15;
            if (o < O) {
                float a = cs[o * SDT + s] + cs[o * SDT + s + 16]
                        + cs[o * SDT + s + 32] + cs[o * SDT + s + 48];
                a += __shfl_xor_sync(0xffffffffu, a, 1);
                a += __shfl_xor_sync(0xffffffffu, a, 2);
                a += __shfl_xor_sync(0xffffffffu, a, 4);
                a += __shfl_xor_sync(0xffffffffu, a, 8);
                if (s == 0) Cv[o] = a;
            }
        }

        // ---- xc[o][c] = sum_i cs[o][i] * xt[i][c]; warp -> 2 o ----
        if (o0 < O) {
            float a00 = 0.f, a01 = 0.f, a10 = 0.f, a11 = 0.f;
            const float* c0r = cs + o0 * SDT;
            const float* c1r = cs + (o0 + 1) * SDT;
            #pragma unroll 4
            for (int i = 0; i < 64; i++) {
                float c0 = c0r[i], c1 = c1r[i];
                float x0 = xt[i * SDT + lane];
                float x1 = xt[i * SDT + lane + 32];
                a00 += c0 * x0; a01 += c0 * x1;
                a10 += c1 * x0; a11 += c1 * x1;
            }
            xc[o0 * SDX + lane] = a00;       xc[o0 * SDX + lane + 32] = a01;
            xc[(o0 + 1) * SDX + lane] = a10; xc[(o0 + 1) * SDX + lane + 32] = a11;
        }
        __syncthreads();

        // ---- y[o] = G[o] xc[o] + C*BW[o]; cooperative coalesced G rows ----
        // 8 lanes per row (8 x 16B = full 128B line), 4 rows per LDG.
        if (o0 < O) {
            const int seg = lane & 7, rgrp = lane >> 3;
            #pragma unroll
            for (int oo = 0; oo < 2; oo++) {
                int o = o0 + oo;
                const __half* Gp = Gh + ((size_t)o << 12) + (seg << 3);
                float4 xq0 = *(const float4*)(xc + o * SDX + seg * 8);
                float4 xq1 = *(const float4*)(xc + o * SDX + seg * 8 + 4);
                float cf = Cv[o];
                #pragma unroll 4
                for (int rb = 0; rb < 64; rb += 4) {
                    int r = rb + rgrp;
                    uint4 g = *(const uint4*)(Gp + (r << 6));
                    float2 t0 = __half22float2(*(__half2*)&g.x);
                    float2 t1 = __half22float2(*(__half2*)&g.y);
                    float2 t2 = __half22float2(*(__half2*)&g.z);
                    float2 t3 = __half22float2(*(__half2*)&g.w);
                    float p = t0.x * xq0.x + t0.y * xq0.y + t1.x * xq0.z + t1.y * xq0.w
                            + t2.x * xq1.x + t2.y * xq1.y + t3.x * xq1.z + t3.y * xq1.w;
                    p += __shfl_xor_sync(0xffffffffu, p, 1);
                    p += __shfl_xor_sync(0xffffffffu, p, 2);
                    p += __shfl_xor_sync(0xffffffffu, p, 4);
                    if (seg == 0)
                        ys[o * SDT + r] = cf * BW[o * 64 + r] + p;
                }
            }
            __syncwarp();
            // ---- |s|^2, sB, alpha per o (full-warp reduction) ----
            #pragma unroll
            for (int oo = 0; oo < 2; oo++) {
                int o = o0 + oo;
                float y0 = ys[o * SDT + lane],      y1 = ys[o * SDT + lane + 32];
                float x0 = xc[o * SDX + lane],      x1 = xc[o * SDX + lane + 32];
                float b0w = BW[o * 64 + lane],      b1w = BW[o * 64 + lane + 32];
                float nn = y0 * x0 + y1 * x1;
                float sb = b0w * x0 + b1w * x1;
                #pragma unroll
                for (int k = 16; k; k >>= 1) {
                    nn += __shfl_xor_sync(0xffffffffu, nn, k);
                    sb += __shfl_xor_sync(0xffffffffu, sb, k);
                }
                if (lane == 0) {
                    float cf = Cv[o];
                    sb += cf * Bn[o];
                    nn += cf * sb;
                    sB[o] = sb;
                    al[o] = (nn / (1.f + nn)) * rsqrtf(nn + 1e-8f);
                }
            }
        }
        __syncthreads();

        if (it < 2) {
            // ---- br[o][i] += alpha[o]*(sum_c ys[o][c]*xs[c][i] + sB[o]) ----
            if (o0 < O) {
                float a00 = 0.f, a01 = 0.f, a10 = 0.f, a11 = 0.f;
                const float* y0r = ys + o0 * SDT;
                const float* y1r = ys + (o0 + 1) * SDT;
                #pragma unroll 4
                for (int c = 0; c < 64; c++) {
                    float y0 = y0r[c], y1 = y1r[c];
                    float x0 = xs[c * SDX + lane];
                    float x1 = xs[c * SDX + lane + 32];
                    a00 += y0 * x0; a01 += y0 * x1;
                    a10 += y1 * x0; a11 += y1 * x1;
                }
                float av0 = al[o0], sv0 = sB[o0];
                float av1 = al[o0 + 1], sv1 = sB[o0 + 1];
                br[o0 * SDT + lane]            += av0 * (a00 + sv0);
                br[o0 * SDT + lane + 32]       += av0 * (a01 + sv0);
                br[(o0 + 1) * SDT + lane]      += av1 * (a10 + sv1);
                br[(o0 + 1) * SDT + lane + 32] += av1 * (a11 + sv1);
            }
            __syncthreads();
        } else {
            // ---- final v[o][d] = alpha[o]*((W xc)[o,d] + C[o]*B[o,d]) ----
            // cooperative coalesced W rows: 16 lanes x 16B = 256B row, 2 rows/LDG
            if (o0 < O) {
                const int s16 = lane & 15, rg2 = lane >> 4;
                #pragma unroll
                for (int oo = 0; oo < 2; oo++) {
                    int o = o0 + oo;
                    float4 xq = *(const float4*)(xc + o * SDX + s16 * 4);
                    float av = al[o], cf = Cv[o];
                    const float* Wp = W + (size_t)(o * 64) * 64 + s16 * 4;
                    #pragma unroll 4
                    for (int db = 0; db < 64; db += 2) {
                        int d = db + rg2;
                        float4 wv = *(const float4*)(Wp + (d << 6));
                        float p = wv.x * xq.x + wv.y * xq.y + wv.z * xq.z + wv.w * xq.w;
                        p += __shfl_xor_sync(0xffffffffu, p, 1);
                        p += __shfl_xor_sync(0xffffffffu, p, 2);
                        p += __shfl_xor_sync(0xffffffffu, p, 4);
                        p += __shfl_xor_sync(0xffffffffu, p, 8);
                        if (s16 == 0) {
                            float v = av * (p + cf * bias[o * 64 + d]);
                            if (is_final) outp[o * 64 + d] = v;
                            else {
                                xs[d * SDX + o] = v;   // x_next[c=d][i=o]
                                xt[o * SDT + d] = v;   // xt_next[i=o][c=d]
                            }
                        }
                    }
                }
            }
            __syncthreads();
        }
    }
}

// ---------------------------------------------------------------------------
// Main fused kernel: conv3x3 + relu + channel squash, then 3+1 capsule layers.
// ---------------------------------------------------------------------------
__global__ void __launch_bounds__(1024, 1)
caps_kernel(const float* __restrict__ gx,  const float* __restrict__ gWb, const float* __restrict__ gbb,
            const float* __restrict__ W1,  const float* __restrict__ b1,
            const float* __restrict__ W2,  const float* __restrict__ b2,
            const float* __restrict__ b_basic, const float* __restrict__ b_cls,
            float* __restrict__ out)
{
    extern __shared__ float sm[];
    int tid = threadIdx.x;
    int b = blockIdx.x;
    float* xs    = sm + XS_OFF;
    float* xt    = sm + XT_OFF;
    float* cvout = sm + XT_OFF;      // conv output staging (stride SDT)
    float* wbs   = sm + WBS_OFF;
    float* fac   = sm + AUX_OFF + 192;
    float* PS    = sm + PS_OFF;

    // load x[b]: xs[c][i] (stride 68)
    const float* xb = gx + (size_t)b * 4096;
    if (tid < 1024) {
        int c = tid >> 4, q = tid & 15;
        float4 v = ((const float4*)(xb + c * 64))[q];
        xs[c * SDX + q * 4 + 0] = v.x;
        xs[c * SDX + q * 4 + 1] = v.y;
        xs[c * SDX + q * 4 + 2] = v.z;
        xs[c * SDX + q * 4 + 3] = v.w;
    }
    // conv weights [64 co][576] at stride 577
    for (int p = tid; p < 36864; p += 1024) {
        int co = p / 576, r = p - co * 576;
        wbs[co * 577 + r] = gWb[p];
    }
    __syncthreads();

    // conv 3x3 SAME: thread = (co, y, xhalf): 4 x-positions each
    {
        int co = tid >> 4, rem = tid & 15;
        int y0 = rem >> 1, h = rem & 1;
        float acc[4];
        float bval = gbb[co];
        #pragma unroll
        for (int j = 0; j < 4; j++) acc[j] = bval;
        const float* wr = wbs + co * 577;
        for (int ci = 0; ci < 64; ci++) {
            const float* xrow = xs + ci * SDX;
            const float* wci = wr + ci * 9;
            float wreg[9];
            #pragma unroll
            for (int k = 0; k < 9; k++) wreg[k] = wci[k];
            #pragma unroll
            for (int ky = 0; ky < 3; ky++) {
                int yy = y0 + ky - 1;
                if (yy >= 0 && yy <= 7) {
                    float rp[6];
                    float4 m = *(const float4*)(xrow + yy * 8 + h * 4);
                    rp[0] = h ? xrow[yy * 8 + 3] : 0.f;
                    rp[1] = m.x; rp[2] = m.y; rp[3] = m.z; rp[4] = m.w;
                    rp[5] = h ? 0.f : xrow[yy * 8 + 4];
                    #pragma unroll
                    for (int kx = 0; kx < 3; kx++) {
                        float wv = wreg[ky * 3 + kx];
                        #pragma unroll
                        for (int j = 0; j < 4; j++) acc[j] += wv * rp[j + kx];
                    }
                }
            }
        }
        #pragma unroll
        for (int j = 0; j < 4; j++)
            cvout[co * SDT + y0 * 8 + h * 4 + j] = fmaxf(acc[j], 0.f);
    }
    __syncthreads();

    // channel squash per spatial position: partials over c-groups of 4
    {
        int i = tid & 63, g = tid >> 6;
        float n2 = 0.f;
        #pragma unroll
        for (int k = 0; k < 4; k++) {
            float hv = cvout[(4 * g + k) * SDT + i];
            n2 += hv * hv;
        }
        PS[g * SDS + i] = n2;
    }
    __syncthreads();
    if (tid < 64) {
        float n2 = 0.f;
        for (int g = 0; g < 16; g++) n2 += PS[g * SDS + tid];
        fac[tid] = (n2 / (1.f + n2)) * rsqrtf(n2 + 1e-8f);
    }
    __syncthreads();
    {
        // write xs (stride 68) and xt (stride 65); must not clobber cvout
        // before reads complete: each thread reads its 4 values first.
        int i = tid & 63, g = tid >> 6;
        float v[4];
        #pragma unroll
        for (int k = 0; k < 4; k++) v[k] = cvout[(4 * g + k) * SDT + i] * fac[i];
        __syncthreads();
        #pragma unroll
        for (int k = 0; k < 4; k++) {
            int c = 4 * g + k;
            xs[c * SDX + i] = v[k];
            xt[i * SDT + c] = v[k];
        }
    }
    __syncthreads();

    for (int L = 0; L < 3; L++)
        cap_layer(64, false, W1, b1, g_G1h, g_BW1, g_Bn1,
                  b_basic + (size_t)(L * 128 + b) * 4096, nullptr, sm, tid);
    cap_layer(10, true, W2, b2, g_G2h, g_BW2, g_Bn2,
              b_cls + (size_t)b * 640, out + (size_t)b * 640, sm, tid);
}

// ---------------------------------------------------------------------------
static const float* pick(void* const* d_in, const int* in_sizes, int n_in, int sz) {
    for (int i = 0; i < n_in; i++)
        if (in_sizes[i] == sz) return (const float*)d_in[i];
    return nullptr;
}

extern "C" void kernel_launch(void* const* d_in, const int* in_sizes, int n_in,
                              void* d_out, int out_size)
{
    const float* x       = pick(d_in, in_sizes, n_in, 128 * 64 * 64);
    const float* Wb      = pick(d_in, in_sizes, n_in, 64 * 64 * 9);
    const float* bb      = pick(d_in, in_sizes, n_in, 64);
    const float* W1      = pick(d_in, in_sizes, n_in, 4096 * 64);
    const float* b1      = pick(d_in, in_sizes, n_in, 4096);
    const float* W2      = pick(d_in, in_sizes, n_in, 640 * 64);
    const float* b2      = pick(d_in, in_sizes, n_in, 640);
    const float* b_basic = pick(d_in, in_sizes, n_in, 3 * 128 * 64 * 64);
    const float* b_cls   = pick(d_in, in_sizes, n_in, 128 * 10 * 64);
    float* out = (float*)d_out;

    cudaFuncSetAttribute(caps_kernel, cudaFuncAttributeMaxDynamicSharedMemorySize, SMEM_BYTES);
    gram_kernel<<<74, 256>>>(W1, b1, W2, b2);
    caps_kernel<<<128, 1024, SMEM_BYTES>>>(x, Wb, bb, W1, b1, W2, b2, b_basic, b_cls, out);
}

// round 4
// speedup vs baseline: 2.3558x; 1.1959x over previous
#include <cuda_runtime.h>
#include <cuda_fp16.h>
#include <math.h>

// ---------------------------------------------------------------------------
// CapsNet forward, fully fused, 1 CTA / batch element, 1024 threads.
// Gram trick: routing never materializes pred.
//   xc[o,c]=sum_i c[o,i]x[c,i];  y[o]=G[o]xc[o]+C*BW[o]  (G=W W^T, fp16)
//   |s|^2=xc.y+C*sB; v=alpha*s;  db[o,i]=alpha*(sum_c y[o,c]x[c,i]+sB)
// Routing GEMMs: 4o x 32c tiles, float4 smem broadcasts (2 LDS : 4 FMA).
// W1 stored fp16 for the 3 intermediate layer outputs; W2 fp32 (final).
// Softmax without max-subtraction (logits bounded << 88).
// ---------------------------------------------------------------------------

#define SDX 68                   // stride for float4-capable arrays
#define SDT 65                   // stride for scalar-only arrays
#define SDS 66                   // staging stride

#define XS_OFF   0               // xs[c][i]   64x68
#define XC_OFF   4352            // xc[o][c]   64x68
#define XT_OFF   8704            // xt[i][c]   64x65  (conv-out staging too)
#define CT_OFF   12864           // ct[i][o]   64x68  (i-major, float4 rows)
#define BR_OFF   17216           // br[o][i]   64x65
#define YT_OFF   21376           // yt[c][o]   64x68  (c-major, float4 rows)
#define AUX_OFF  25728           // Cv|al|sB|fac
#define PS_OFF   25984           // 16x66 staging
#define WBS_OFF  12864           // conv weights overlay 64x577
#define SMEM_FLOATS 49792
#define SMEM_BYTES (SMEM_FLOATS * 4)

__device__ __align__(16) __half g_G1h[64 * 64 * 64];
__device__ __align__(16) __half g_G2h[10 * 64 * 64];
__device__ __align__(16) __half g_W1h[64 * 64 * 64];
__device__ float g_BW1[64 * 64];
__device__ float g_Bn1[64];
__device__ float g_BW2[10 * 64];
__device__ float g_Bn2[16];

// ---------------------------------------------------------------------------
__global__ void gram_kernel(const float* __restrict__ W1, const float* __restrict__ b1,
                            const float* __restrict__ W2, const float* __restrict__ b2)
{
    __shared__ float ws[64 * SDX];
    __shared__ float bsv[64];
    int blk = blockIdx.x;
    const float* W;
    const float* bias;
    __half* G; float* BW; float* Bn;
    int o;
    if (blk < 64) { o = blk;      W = W1; bias = b1; G = g_G1h + o * 4096; BW = g_BW1 + o * 64; Bn = g_Bn1 + o; }
    else          { o = blk - 64; W = W2; bias = b2; G = g_G2h + o * 4096; BW = g_BW2 + o * 64; Bn = g_Bn2 + o; }
    int tid = threadIdx.x;  // 256

    for (int p = tid; p < 64 * 16; p += 256) {
        int d = p >> 4, q = p & 15;
        float4 v = ((const float4*)(W + (o * 64 + d) * 64))[q];
        ws[d * SDX + q * 4 + 0] = v.x;
        ws[d * SDX + q * 4 + 1] = v.y;
        ws[d * SDX + q * 4 + 2] = v.z;
        ws[d * SDX + q * 4 + 3] = v.w;
    }
    if (tid < 64) bsv[tid] = bias[o * 64 + tid];
    __syncthreads();

    for (int p = tid; p < 64 * 16; p += 256) {
        int c = p >> 4, c4 = (p & 15) * 4;
        float a0 = 0.f, a1 = 0.f, a2 = 0.f, a3 = 0.f;
        #pragma unroll 4
        for (int d = 0; d < 64; d++) {
            float wc = ws[d * SDX + c];
            a0 += wc * ws[d * SDX + c4 + 0];
            a1 += wc * ws[d * SDX + c4 + 1];
            a2 += wc * ws[d * SDX + c4 + 2];
            a3 += wc * ws[d * SDX + c4 + 3];
        }
        G[c * 64 + c4 + 0] = __float2half_rn(a0);
        G[c * 64 + c4 + 1] = __float2half_rn(a1);
        G[c * 64 + c4 + 2] = __float2half_rn(a2);
        G[c * 64 + c4 + 3] = __float2half_rn(a3);
    }
    // fp16 copy of W1 rows for this o (intermediate layer outputs)
    if (blk < 64) {
        for (int p = tid; p < 2048; p += 256) {
            int d = p >> 5, c2 = (p & 31) * 2;
            __half2 hv = __floats2half2_rn(ws[d * SDX + c2], ws[d * SDX + c2 + 1]);
            *((__half2*)(g_W1h + ((size_t)o << 12) + d * 64 + c2)) = hv;
        }
    }
    if (tid < 64) {
        float acc = 0.f;
        for (int d = 0; d < 64; d++) acc += bsv[d] * ws[d * SDX + tid];
        BW[tid] = acc;
    }
    if (tid == 64) {
        float acc = 0.f;
        for (int d = 0; d < 64; d++) acc += bsv[d] * bsv[d];
        *Bn = acc;
    }
}

// ---------------------------------------------------------------------------
// One capsule layer, 3 routing iterations. O = 64 or 10.
// ---------------------------------------------------------------------------
__device__ __forceinline__ void cap_layer(
    int O, bool is_final,
    const float* __restrict__ W2f, const __half* __restrict__ W1h,
    const float* __restrict__ bias,
    const __half* __restrict__ Gh, const float* __restrict__ BW, const float* __restrict__ Bn,
    const float* __restrict__ b0, float* __restrict__ outp,
    float* sm, int tid)
{
    float* xs = sm + XS_OFF;
    float* xc = sm + XC_OFF;
    float* xt = sm + XT_OFF;
    float* ct = sm + CT_OFF;
    float* br = sm + BR_OFF;
    float* yt = sm + YT_OFF;
    float* Cv = sm + AUX_OFF;
    float* al = sm + AUX_OFF + 64;
    float* sB = sm + AUX_OFF + 128;
    float* PS = sm + PS_OFF;

    const int w = tid >> 5, lane = tid & 31;
    const int o0y = w * 2;                    // y-loop / W-pass mapping (2 o per warp)
    const int o0t = (w >> 1) * 4;             // GEMM tiles: 4 o per warp pair
    const int hb = (w & 1) * 32;              // c/i half
    const int ii = tid & 63, gg = tid >> 6;
    const int ngrp = (O + 3) >> 2;

    // load routing logits br[o][i]
    for (int p = tid; p < O * 64; p += 1024)
        br[(p >> 6) * SDT + (p & 63)] = b0[p];
    __syncthreads();

    for (int it = 0; it < 3; it++) {
        // ---- softmax over o (no max-subtract; logits bounded) ----
        float ev0 = 0.f, ev1 = 0.f, ev2 = 0.f, ev3 = 0.f;
        if (gg < ngrp) {
            int o = gg * 4;
            ev0 = __expf(br[o * SDT + ii]);
            ev1 = (o + 1 < O) ? __expf(br[(o + 1) * SDT + ii]) : 0.f;
            ev2 = (o + 2 < O) ? __expf(br[(o + 2) * SDT + ii]) : 0.f;
            ev3 = (o + 3 < O) ? __expf(br[(o + 3) * SDT + ii]) : 0.f;
            PS[gg * SDS + ii] = ev0 + ev1 + ev2 + ev3;
        }
        __syncthreads();
        float gsum = 0.f;
        for (int g2 = 0; g2 < ngrp; g2++) gsum += PS[g2 * SDS + ii];
        float ginv = 1.f / gsum;
        if (gg < ngrp) {
            float4 c4 = make_float4(ev0 * ginv, ev1 * ginv, ev2 * ginv, ev3 * ginv);
            *(float4*)(ct + ii * SDX + gg * 4) = c4;   // ct[i][o], STS.128
        }
        __syncthreads();

        // ---- Cv[o] = sum_i c[o,i] (16 threads per o, column sums of ct) ----
        {
            int o = tid >> 4, s = tid & 15;
            if (o < O) {
                float a = ct[s * SDX + o] + ct[(s + 16) * SDX + o]
                        + ct[(s + 32) * SDX + o] + ct[(s + 48) * SDX + o];
                a += __shfl_xor_sync(0xffffffffu, a, 1);
                a += __shfl_xor_sync(0xffffffffu, a, 2);
                a += __shfl_xor_sync(0xffffffffu, a, 4);
                a += __shfl_xor_sync(0xffffffffu, a, 8);
                if (s == 0) Cv[o] = a;
            }
        }

        // ---- xc[o][c] = sum_i ct[i][o]*xt[i][c]; 4o x 32c tile per warp ----
        if (o0t < O) {
            float a0 = 0.f, a1 = 0.f, a2 = 0.f, a3 = 0.f;
            #pragma unroll 4
            for (int i = 0; i < 64; i++) {
                float4 cv = *(const float4*)(ct + i * SDX + o0t);   // bcast
                float xv = xt[i * SDT + hb + lane];                 // coalesced
                a0 += cv.x * xv; a1 += cv.y * xv;
                a2 += cv.z * xv; a3 += cv.w * xv;
            }
            xc[o0t * SDX + hb + lane] = a0;
            if (o0t + 1 < O) xc[(o0t + 1) * SDX + hb + lane] = a1;
            if (o0t + 2 < O) xc[(o0t + 2) * SDX + hb + lane] = a2;
            if (o0t + 3 < O) xc[(o0t + 3) * SDX + hb + lane] = a3;
        }
        __syncthreads();

        // ---- y[o] = G[o] xc[o] + C*BW[o]; cooperative coalesced G rows ----
        if (o0y < O) {
            const int seg = lane & 7, rgrp = lane >> 3;
            #pragma unroll
            for (int oo = 0; oo < 2; oo++) {
                int o = o0y + oo;
                const __half* Gp = Gh + ((size_t)o << 12) + (seg << 3);
                float4 xq0 = *(const float4*)(xc + o * SDX + seg * 8);
                float4 xq1 = *(const float4*)(xc + o * SDX + seg * 8 + 4);
                float cf = Cv[o];
                #pragma unroll 4
                for (int rb = 0; rb < 64; rb += 4) {
                    int r = rb + rgrp;
                    uint4 g = *(const uint4*)(Gp + (r << 6));
                    float2 t0 = __half22float2(*(__half2*)&g.x);
                    float2 t1 = __half22float2(*(__half2*)&g.y);
                    float2 t2 = __half22float2(*(__half2*)&g.z);
                    float2 t3 = __half22float2(*(__half2*)&g.w);
                    float p = t0.x * xq0.x + t0.y * xq0.y + t1.x * xq0.z + t1.y * xq0.w
                            + t2.x * xq1.x + t2.y * xq1.y + t3.x * xq1.z + t3.y * xq1.w;
                    p += __shfl_xor_sync(0xffffffffu, p, 1);
                    p += __shfl_xor_sync(0xffffffffu, p, 2);
                    p += __shfl_xor_sync(0xffffffffu, p, 4);
                    if (seg == 0)
                        yt[r * SDX + o] = cf * BW[o * 64 + r] + p;   // transposed
                }
            }
            __syncwarp();
            // ---- |s|^2, sB, alpha per o ----
            #pragma unroll
            for (int oo = 0; oo < 2; oo++) {
                int o = o0y + oo;
                float y0 = yt[lane * SDX + o],  y1 = yt[(lane + 32) * SDX + o];
                float x0 = xc[o * SDX + lane],  x1 = xc[o * SDX + lane + 32];
                float b0w = BW[o * 64 + lane],  b1w = BW[o * 64 + lane + 32];
                float nn = y0 * x0 + y1 * x1;
                float sb = b0w * x0 + b1w * x1;
                #pragma unroll
                for (int k = 16; k; k >>= 1) {
                    nn += __shfl_xor_sync(0xffffffffu, nn, k);
                    sb += __shfl_xor_sync(0xffffffffu, sb, k);
                }
                if (lane == 0) {
                    float cf = Cv[o];
                    sb += cf * Bn[o];
                    nn += cf * sb;
                    sB[o] = sb;
                    al[o] = (nn / (1.f + nn)) * rsqrtf(nn + 1e-8f);
                }
            }
        }
        __syncthreads();

        if (it < 2) {
            // ---- br[o][i] += alpha*(sum_c yt[c][o]*xs[c][i] + sB); 4o x 32i ----
            if (o0t < O) {
                float a0 = 0.f, a1 = 0.f, a2 = 0.f, a3 = 0.f;
                #pragma unroll 4
                for (int c = 0; c < 64; c++) {
                    float4 yv = *(const float4*)(yt + c * SDX + o0t);  // bcast
                    float xv = xs[c * SDX + hb + lane];                // coalesced
                    a0 += yv.x * xv; a1 += yv.y * xv;
                    a2 += yv.z * xv; a3 += yv.w * xv;
                }
                br[o0t * SDT + hb + lane] += al[o0t] * (a0 + sB[o0t]);
                if (o0t + 1 < O) br[(o0t + 1) * SDT + hb + lane] += al[o0t + 1] * (a1 + sB[o0t + 1]);
                if (o0t + 2 < O) br[(o0t + 2) * SDT + hb + lane] += al[o0t + 2] * (a2 + sB[o0t + 2]);
                if (o0t + 3 < O) br[(o0t + 3) * SDT + hb + lane] += al[o0t + 3] * (a3 + sB[o0t + 3]);
            }
            __syncthreads();
        } else if (!is_final) {
            // ---- v[o][d] = alpha*((W1 xc)[o,d] + C*B[o,d]); fp16 W rows ----
            if (o0y < O) {
                const int seg = lane & 7, rg = lane >> 3;
                #pragma unroll
                for (int oo = 0; oo < 2; oo++) {
                    int o = o0y + oo;
                    float4 xq0 = *(const float4*)(xc + o * SDX + seg * 8);
                    float4 xq1 = *(const float4*)(xc + o * SDX + seg * 8 + 4);
                    float av = al[o], cf = Cv[o];
                    const __half* Wp = W1h + ((size_t)o << 12) + (seg << 3);
                    #pragma unroll 4
                    for (int db_ = 0; db_ < 64; db_ += 4) {
                        int d = db_ + rg;
                        uint4 g = *(const uint4*)(Wp + (d << 6));
                        float2 t0 = __half22float2(*(__half2*)&g.x);
                        float2 t1 = __half22float2(*(__half2*)&g.y);
                        float2 t2 = __half22float2(*(__half2*)&g.z);
                        float2 t3 = __half22float2(*(__half2*)&g.w);
                        float p = t0.x * xq0.x + t0.y * xq0.y + t1.x * xq0.z + t1.y * xq0.w
                                + t2.x * xq1.x + t2.y * xq1.y + t3.x * xq1.z + t3.y * xq1.w;
                        p += __shfl_xor_sync(0xffffffffu, p, 1);
                        p += __shfl_xor_sync(0xffffffffu, p, 2);
                        p += __shfl_xor_sync(0xffffffffu, p, 4);
                        if (seg == 0) {
                            float v = av * (p + cf * bias[o * 64 + d]);
                            xs[d * SDX + o] = v;     // x_next[c=d][i=o]
                            xt[o * SDT + d] = v;     // xt_next[i=o][c=d]
                        }
                    }
                }
            }
            __syncthreads();
        } else {
            // ---- final: v[o][d] via fp32 W2 (16-lane rows) -> gmem ----
            if (o0y < O) {
                const int s16 = lane & 15, rg2 = lane >> 4;
                #pragma unroll
                for (int oo = 0; oo < 2; oo++) {
                    int o = o0y + oo;
                    float4 xq = *(const float4*)(xc + o * SDX + s16 * 4);
                    float av = al[o], cf = Cv[o];
                    const float* Wp = W2f + (size_t)(o * 64) * 64 + s16 * 4;
                    #pragma unroll 4
                    for (int db_ = 0; db_ < 64; db_ += 2) {
                        int d = db_ + rg2;
                        float4 wv = *(const float4*)(Wp + (d << 6));
                        float p = wv.x * xq.x + wv.y * xq.y + wv.z * xq.z + wv.w * xq.w;
                        p += __shfl_xor_sync(0xffffffffu, p, 1);
                        p += __shfl_xor_sync(0xffffffffu, p, 2);
                        p += __shfl_xor_sync(0xffffffffu, p, 4);
                        p += __shfl_xor_sync(0xffffffffu, p, 8);
                        if (s16 == 0)
                            outp[o * 64 + d] = av * (p + cf * bias[o * 64 + d]);
                    }
                }
            }
            __syncthreads();
        }
    }
}

// ---------------------------------------------------------------------------
// Main fused kernel: conv3x3 + relu + channel squash, then 3+1 capsule layers.
// ---------------------------------------------------------------------------
__global__ void __launch_bounds__(1024, 1)
caps_kernel(const float* __restrict__ gx,  const float* __restrict__ gWb, const float* __restrict__ gbb,
            const float* __restrict__ W1,  const float* __restrict__ b1,
            const float* __restrict__ W2,  const float* __restrict__ b2,
            const float* __restrict__ b_basic, const float* __restrict__ b_cls,
            float* __restrict__ out)
{
    extern __shared__ float sm[];
    int tid = threadIdx.x;
    int b = blockIdx.x;
    float* xs    = sm + XS_OFF;
    float* xt    = sm + XT_OFF;
    float* cvout = sm + XT_OFF;      // conv output staging (stride SDT)
    float* wbs   = sm + WBS_OFF;
    float* fac   = sm + AUX_OFF + 192;
    float* PS    = sm + PS_OFF;

    // load x[b]: xs[c][i] (stride 68)
    const float* xb = gx + (size_t)b * 4096;
    {
        int c = tid >> 4, q = tid & 15;
        float4 v = ((const float4*)(xb + c * 64))[q];
        xs[c * SDX + q * 4 + 0] = v.x;
        xs[c * SDX + q * 4 + 1] = v.y;
        xs[c * SDX + q * 4 + 2] = v.z;
        xs[c * SDX + q * 4 + 3] = v.w;
    }
    // conv weights [64 co][576] at stride 577
    for (int p = tid; p < 36864; p += 1024) {
        int co = p / 576, r = p - co * 576;
        wbs[co * 577 + r] = gWb[p];
    }
    __syncthreads();

    // conv 3x3 SAME. Warp w: position group pg = w>>1 -> (y0, xhalf);
    // lane -> co (coalesced weight loads, broadcast x loads).
    {
        int wA = tid >> 5, lane = tid & 31;
        int pg = wA >> 1;
        int y0 = pg >> 1, h = pg & 1;
        int co = (wA & 1) * 32 + lane;
        float acc0, acc1, acc2, acc3;
        {
            float bval = gbb[co];
            acc0 = acc1 = acc2 = acc3 = bval;
        }
        const float* wr = wbs + co * 577;
        for (int ci = 0; ci < 64; ci++) {
            const float* xrow = xs + ci * SDX;
            const float* wci = wr + ci * 9;
            float w0 = wci[0], w1 = wci[1], w2 = wci[2];
            float w3 = wci[3], w4 = wci[4], w5 = wci[5];
            float w6 = wci[6], w7 = wci[7], w8 = wci[8];
            #pragma unroll
            for (int ky = 0; ky < 3; ky++) {
                int yy = y0 + ky - 1;
                if (yy >= 0 && yy <= 7) {
                    float4 m = *(const float4*)(xrow + yy * 8 + h * 4);  // bcast
                    float rp0 = h ? xrow[yy * 8 + 3] : 0.f;
                    float rp5 = h ? 0.f : xrow[yy * 8 + 4];
                    float ta = (ky == 0) ? w0 : (ky == 1) ? w3 : w6;
                    float tb = (ky == 0) ? w1 : (ky == 1) ? w4 : w7;
                    float tc = (ky == 0) ? w2 : (ky == 1) ? w5 : w8;
                    acc0 += ta * rp0 + tb * m.x + tc * m.y;
                    acc1 += ta * m.x + tb * m.y + tc * m.z;
                    acc2 += ta * m.y + tb * m.z + tc * m.w;
                    acc3 += ta * m.z + tb * m.w + tc * rp5;
                }
            }
        }
        int base = y0 * 8 + h * 4;
        cvout[co * SDT + base + 0] = fmaxf(acc0, 0.f);
        cvout[co * SDT + base + 1] = fmaxf(acc1, 0.f);
        cvout[co * SDT + base + 2] = fmaxf(acc2, 0.f);
        cvout[co * SDT + base + 3] = fmaxf(acc3, 0.f);
    }
    __syncthreads();

    // channel squash per spatial position
    {
        int i = tid & 63, g = tid >> 6;
        float n2 = 0.f;
        #pragma unroll
        for (int k = 0; k < 4; k++) {
            float hv = cvout[(4 * g + k) * SDT + i];
            n2 += hv * hv;
        }
        PS[g * SDS + i] = n2;
    }
    __syncthreads();
    if (tid < 64) {
        float n2 = 0.f;
        for (int g = 0; g < 16; g++) n2 += PS[g * SDS + tid];
        fac[tid] = (n2 / (1.f + n2)) * rsqrtf(n2 + 1e-8f);
    }
    __syncthreads();
    {
        int i = tid & 63, g = tid >> 6;
        float v[4];
        #pragma unroll
        for (int k = 0; k < 4; k++) v[k] = cvout[(4 * g + k) * SDT + i] * fac[i];
        __syncthreads();
        #pragma unroll
        for (int k = 0; k < 4; k++) {
            int c = 4 * g + k;
            xs[c * SDX + i] = v[k];
            xt[i * SDT + c] = v[k];
        }
    }
    __syncthreads();

    for (int L = 0; L < 3; L++)
        cap_layer(64, false, nullptr, g_W1h, b1, g_G1h, g_BW1, g_Bn1,
                  b_basic + (size_t)(L * 128 + b) * 4096, nullptr, sm, tid);
    cap_layer(10, true, W2, nullptr, b2, g_G2h, g_BW2, g_Bn2,
              b_cls + (size_t)b * 640, out + (size_t)b * 640, sm, tid);
}

// ---------------------------------------------------------------------------
static const float* pick(void* const* d_in, const int* in_sizes, int n_in, int sz) {
    for (int i = 0; i < n_in; i++)
        if (in_sizes[i] == sz) return (const float*)d_in[i];
    return nullptr;
}

extern "C" void kernel_launch(void* const* d_in, const int* in_sizes, int n_in,
                              void* d_out, int out_size)
{
    const float* x       = pick(d_in, in_sizes, n_in, 128 * 64 * 64);
    const float* Wb      = pick(d_in, in_sizes, n_in, 64 * 64 * 9);
    const float* bb      = pick(d_in, in_sizes, n_in, 64);
    const float* W1      = pick(d_in, in_sizes, n_in, 4096 * 64);
    const float* b1      = pick(d_in, in_sizes, n_in, 4096);
    const float* W2      = pick(d_in, in_sizes, n_in, 640 * 64);
    const float* b2      = pick(d_in, in_sizes, n_in, 640);
    const float* b_basic = pick(d_in, in_sizes, n_in, 3 * 128 * 64 * 64);
    const float* b_cls   = pick(d_in, in_sizes, n_in, 128 * 10 * 64);
    float* out = (float*)d_out;

    cudaFuncSetAttribute(caps_kernel, cudaFuncAttributeMaxDynamicSharedMemorySize, SMEM_BYTES);
    gram_kernel<<<74, 256>>>(W1, b1, W2, b2);
    caps_kernel<<<128, 1024, SMEM_BYTES>>>(x, Wb, bb, W1, b1, W2, b2, b_basic, b_cls, out);
}

// round 5
// speedup vs baseline: 2.3592x; 1.0015x over previous
#include <cuda_runtime.h>
#include <cuda_fp16.h>
#include <math.h>

// ---------------------------------------------------------------------------
// CapsNet forward, fully fused, 1 CTA / batch element, 1024 threads.
// Gram trick: routing never materializes pred.
//   xc[o,c]=sum_i c[o,i]x[c,i];  y[o]=G[o]xc[o]+C*BW[o]  (G=W W^T, fp16)
//   |s|^2=xc.y+C*sB; v=alpha*s;  db[o,i]=alpha*(sum_c y[o,c]x[c,i]+sB)
// Logits are never stored: E=exp(b) is maintained directly (softmax is
// shift-invariant per input capsule, and E<=e^3 so no overflow), with the
// exp update fused into the db GEMM epilogue. GEMMs use 8o x 32c register
// tiles (2 float4 broadcasts + 1 coalesced LDS per k-step).
// ---------------------------------------------------------------------------

#define SD  68                   // row stride (floats), float4-capable
#define SDS 66                   // staging stride

#define XS_OFF   0               // xs[c][i]   64x68
#define XT_OFF   4352            // xt[i][c]   64x68
#define XC_OFF   8704            // xc[o][c]   64x68 (conv-out staging too)
#define CT_OFF   13056           // ct[i][o]   64x68: E, then normalized c
#define YT_OFF   17408           // yt[c][o]   64x68
#define AUX_OFF  21760           // ginv|Cv|al|sB|CvP[128]|fac
#define PS_OFF   22272           // 16x66 partial sums
#define WBS_OFF  13056           // conv weights overlay 64x577
#define SMEM_FLOATS 49984
#define SMEM_BYTES (SMEM_FLOATS * 4)

__device__ __align__(16) __half g_G1h[64 * 64 * 64];
__device__ __align__(16) __half g_G2h[10 * 64 * 64];
__device__ __align__(16) __half g_W1h[64 * 64 * 64];
__device__ float g_BW1[64 * 64];
__device__ float g_Bn1[64];
__device__ float g_BW2[10 * 64];
__device__ float g_Bn2[16];

// ---------------------------------------------------------------------------
__global__ void gram_kernel(const float* __restrict__ W1, const float* __restrict__ b1,
                            const float* __restrict__ W2, const float* __restrict__ b2)
{
    __shared__ float ws[64 * SD];
    __shared__ float bsv[64];
    int blk = blockIdx.x;
    const float* W;
    const float* bias;
    __half* G; float* BW; float* Bn;
    int o;
    if (blk < 64) { o = blk;      W = W1; bias = b1; G = g_G1h + o * 4096; BW = g_BW1 + o * 64; Bn = g_Bn1 + o; }
    else          { o = blk - 64; W = W2; bias = b2; G = g_G2h + o * 4096; BW = g_BW2 + o * 64; Bn = g_Bn2 + o; }
    int tid = threadIdx.x;  // 256

    for (int p = tid; p < 64 * 16; p += 256) {
        int d = p >> 4, q = p & 15;
        float4 v = ((const float4*)(W + (o * 64 + d) * 64))[q];
        ws[d * SD + q * 4 + 0] = v.x;
        ws[d * SD + q * 4 + 1] = v.y;
        ws[d * SD + q * 4 + 2] = v.z;
        ws[d * SD + q * 4 + 3] = v.w;
    }
    if (tid < 64) bsv[tid] = bias[o * 64 + tid];
    __syncthreads();

    for (int p = tid; p < 64 * 16; p += 256) {
        int c = p >> 4, c4 = (p & 15) * 4;
        float a0 = 0.f, a1 = 0.f, a2 = 0.f, a3 = 0.f;
        #pragma unroll 4
        for (int d = 0; d < 64; d++) {
            float wc = ws[d * SD + c];
            a0 += wc * ws[d * SD + c4 + 0];
            a1 += wc * ws[d * SD + c4 + 1];
            a2 += wc * ws[d * SD + c4 + 2];
            a3 += wc * ws[d * SD + c4 + 3];
        }
        G[c * 64 + c4 + 0] = __float2half_rn(a0);
        G[c * 64 + c4 + 1] = __float2half_rn(a1);
        G[c * 64 + c4 + 2] = __float2half_rn(a2);
        G[c * 64 + c4 + 3] = __float2half_rn(a3);
    }
    if (blk < 64) {
        for (int p = tid; p < 2048; p += 256) {
            int d = p >> 5, c2 = (p & 31) * 2;
            __half2 hv = __floats2half2_rn(ws[d * SD + c2], ws[d * SD + c2 + 1]);
            *((__half2*)(g_W1h + ((size_t)o << 12) + d * 64 + c2)) = hv;
        }
    }
    if (tid < 64) {
        float acc = 0.f;
        for (int d = 0; d < 64; d++) acc += bsv[d] * ws[d * SD + tid];
        BW[tid] = acc;
    }
    if (tid == 64) {
        float acc = 0.f;
        for (int d = 0; d < 64; d++) acc += bsv[d] * bsv[d];
        *Bn = acc;
    }
}

// ---------------------------------------------------------------------------
// One capsule layer, 3 routing iterations. O = 64 or 10.
// ---------------------------------------------------------------------------
__device__ __forceinline__ void cap_layer(
    int O, bool is_final,
    const float* __restrict__ W2f, const __half* __restrict__ W1h,
    const float* __restrict__ bias,
    const __half* __restrict__ Gh, const float* __restrict__ BW, const float* __restrict__ Bn,
    const float* __restrict__ b0, float* __restrict__ outp,
    float* sm, int tid)
{
    float* xs   = sm + XS_OFF;
    float* xt   = sm + XT_OFF;
    float* xc   = sm + XC_OFF;
    float* ct   = sm + CT_OFF;
    float* yt   = sm + YT_OFF;
    float* ginv = sm + AUX_OFF;
    float* Cv   = sm + AUX_OFF + 64;
    float* al   = sm + AUX_OFF + 128;
    float* sB   = sm + AUX_OFF + 192;
    float* CvP  = sm + AUX_OFF + 256;
    float* PS   = sm + PS_OFF;

    const int w = tid >> 5, lane = tid & 31;
    const int ii = tid & 63, gg = tid >> 6;
    const int ngrp = (O + 3) >> 2;
    const int nog  = (O + 7) >> 3;
    const int o0t  = (w >> 1) << 3;       // 8-o tile base (GEMM passes)
    const int hb2  = (w & 1) << 5;        // 32-wide half
    const int o0y  = w << 1;              // y-pass: 2 o per warp

    // ---- E0 = exp(b0), with per-i partial sums ----
    if (gg < ngrp) {
        int ob = gg << 2;
        float e0 = __expf(b0[ob * 64 + ii]);
        float e1 = (ob + 1 < O) ? __expf(b0[(ob + 1) * 64 + ii]) : 0.f;
        float e2 = (ob + 2 < O) ? __expf(b0[(ob + 2) * 64 + ii]) : 0.f;
        float e3 = (ob + 3 < O) ? __expf(b0[(ob + 3) * 64 + ii]) : 0.f;
        *(float4*)(ct + ii * SD + ob) = make_float4(e0, e1, e2, e3);
        PS[gg * SDS + ii] = e0 + e1 + e2 + e3;
    }
    __syncthreads();

    for (int it = 0; it < 3; it++) {
        // ---- ginv[i] = 1 / sum_o E ----
        int nrows = (it == 0) ? ngrp : nog;
        if (tid < 64) {
            float s = 0.f;
            for (int g = 0; g < nrows; g++) s += PS[g * SDS + tid];
            ginv[tid] = 1.f / s;
        }
        __syncthreads();

        // ---- normalize ct in place; Cv partials via register shfl ----
        if (gg < ngrp) {
            float gi = ginv[ii];
            float4 e4 = *(float4*)(ct + ii * SD + (gg << 2));
            e4.x *= gi; e4.y *= gi; e4.z *= gi; e4.w *= gi;
            *(float4*)(ct + ii * SD + (gg << 2)) = e4;
            float s0 = e4.x, s1 = e4.y, s2 = e4.z, s3 = e4.w;
            #pragma unroll
            for (int k = 16; k; k >>= 1) {
                s0 += __shfl_xor_sync(0xffffffffu, s0, k);
                s1 += __shfl_xor_sync(0xffffffffu, s1, k);
                s2 += __shfl_xor_sync(0xffffffffu, s2, k);
                s3 += __shfl_xor_sync(0xffffffffu, s3, k);
            }
            if (lane == 0) {
                float* dst = CvP + ((tid >> 5) & 1) * 64 + (gg << 2);
                dst[0] = s0; dst[1] = s1; dst[2] = s2; dst[3] = s3;
            }
        }
        __syncthreads();
        if (tid < O) Cv[tid] = CvP[tid] + CvP[64 + tid];

        // ---- xc[o][c] = sum_i c[o,i]*xt[i][c]; 8o x 32c tile / warp ----
        if (w < 16 && o0t < O) {
            float a0 = 0.f, a1 = 0.f, a2 = 0.f, a3 = 0.f;
            float a4 = 0.f, a5 = 0.f, a6 = 0.f, a7 = 0.f;
            #pragma unroll 4
            for (int i = 0; i < 64; i++) {
                float4 cA = *(const float4*)(ct + i * SD + o0t);      // bcast
                float4 cB = *(const float4*)(ct + i * SD + o0t + 4);  // bcast
                float xv = xt[i * SD + hb2 + lane];                   // coalesced
                a0 += cA.x * xv; a1 += cA.y * xv; a2 += cA.z * xv; a3 += cA.w * xv;
                a4 += cB.x * xv; a5 += cB.y * xv; a6 += cB.z * xv; a7 += cB.w * xv;
            }
            xc[o0t * SD + hb2 + lane] = a0;
            if (o0t + 1 < O) xc[(o0t + 1) * SD + hb2 + lane] = a1;
            if (o0t + 2 < O) xc[(o0t + 2) * SD + hb2 + lane] = a2;
            if (o0t + 3 < O) xc[(o0t + 3) * SD + hb2 + lane] = a3;
            if (o0t + 4 < O) xc[(o0t + 4) * SD + hb2 + lane] = a4;
            if (o0t + 5 < O) xc[(o0t + 5) * SD + hb2 + lane] = a5;
            if (o0t + 6 < O) xc[(o0t + 6) * SD + hb2 + lane] = a6;
            if (o0t + 7 < O) xc[(o0t + 7) * SD + hb2 + lane] = a7;
        }
        __syncthreads();

        // ---- y[o] = G[o] xc[o] + C*BW[o]; cooperative coalesced G rows ----
        if (o0y < O) {
            const int seg = lane & 7, rgrp = lane >> 3;
            #pragma unroll
            for (int oo = 0; oo < 2; oo++) {
                int o = o0y + oo;
                const __half* Gp = Gh + ((size_t)o << 12) + (seg << 3);
                float4 xq0 = *(const float4*)(xc + o * SD + seg * 8);
                float4 xq1 = *(const float4*)(xc + o * SD + seg * 8 + 4);
                float cf = Cv[o];
                #pragma unroll 4
                for (int rb = 0; rb < 64; rb += 4) {
                    int r = rb + rgrp;
                    uint4 g = *(const uint4*)(Gp + (r << 6));
                    float2 t0 = __half22float2(*(__half2*)&g.x);
                    float2 t1 = __half22float2(*(__half2*)&g.y);
                    float2 t2 = __half22float2(*(__half2*)&g.z);
                    float2 t3 = __half22float2(*(__half2*)&g.w);
                    float p = t0.x * xq0.x + t0.y * xq0.y + t1.x * xq0.z + t1.y * xq0.w
                            + t2.x * xq1.x + t2.y * xq1.y + t3.x * xq1.z + t3.y * xq1.w;
                    p += __shfl_xor_sync(0xffffffffu, p, 1);
                    p += __shfl_xor_sync(0xffffffffu, p, 2);
                    p += __shfl_xor_sync(0xffffffffu, p, 4);
                    if (seg == 0)
                        yt[r * SD + o] = cf * BW[o * 64 + r] + p;
                }
            }
            __syncwarp();
            // ---- |s|^2, sB, alpha per o ----
            #pragma unroll
            for (int oo = 0; oo < 2; oo++) {
                int o = o0y + oo;
                float y0 = yt[lane * SD + o],  y1 = yt[(lane + 32) * SD + o];
                float x0 = xc[o * SD + lane],  x1 = xc[o * SD + lane + 32];
                float b0w = BW[o * 64 + lane], b1w = BW[o * 64 + lane + 32];
                float nn = y0 * x0 + y1 * x1;
                float sb = b0w * x0 + b1w * x1;
                #pragma unroll
                for (int k = 16; k; k >>= 1) {
                    nn += __shfl_xor_sync(0xffffffffu, nn, k);
                    sb += __shfl_xor_sync(0xffffffffu, sb, k);
                }
                if (lane == 0) {
                    float cf = Cv[o];
                    sb += cf * Bn[o];
                    nn += cf * sb;
                    sB[o] = sb;
                    al[o] = (nn / (1.f + nn)) * rsqrtf(nn + 1e-8f);
                }
            }
        }
        __syncthreads();

        if (it < 2) {
            // ---- db GEMM fused with E update: E = c * exp(db) ----
            if (w < 16 && o0t < O) {
                int i = hb2 + lane;
                float a0 = 0.f, a1 = 0.f, a2 = 0.f, a3 = 0.f;
                float a4 = 0.f, a5 = 0.f, a6 = 0.f, a7 = 0.f;
                #pragma unroll 4
                for (int c = 0; c < 64; c++) {
                    float4 yA = *(const float4*)(yt + c * SD + o0t);      // bcast
                    float4 yB = *(const float4*)(yt + c * SD + o0t + 4);  // bcast
                    float xv = xs[c * SD + i];                            // coalesced
                    a0 += yA.x * xv; a1 += yA.y * xv; a2 += yA.z * xv; a3 += yA.w * xv;
                    a4 += yB.x * xv; a5 += yB.y * xv; a6 += yB.z * xv; a7 += yB.w * xv;
                }
                float4 cA = *(float4*)(ct + i * SD + o0t);
                float4 cB = *(float4*)(ct + i * SD + o0t + 4);
                float acc[8] = {a0, a1, a2, a3, a4, a5, a6, a7};
                float cin[8] = {cA.x, cA.y, cA.z, cA.w, cB.x, cB.y, cB.z, cB.w};
                float e[8];
                float ssum = 0.f;
                #pragma unroll
                for (int j = 0; j < 8; j++) {
                    int o = o0t + j;
                    if (o < O) {
                        float db = al[o] * (acc[j] + sB[o]);
                        e[j] = cin[j] * __expf(db);
                    } else e[j] = 0.f;
                    ssum += e[j];
                }
                *(float4*)(ct + i * SD + o0t)     = make_float4(e[0], e[1], e[2], e[3]);
                *(float4*)(ct + i * SD + o0t + 4) = make_float4(e[4], e[5], e[6], e[7]);
                PS[(o0t >> 3) * SDS + i] = ssum;
            }
            __syncthreads();
        } else if (!is_final) {
            // ---- v[o][d] = alpha*((W1 xc)[o,d] + C*B[o,d]); fp16 W rows ----
            if (o0y < O) {
                const int seg = lane & 7, rg = lane >> 3;
                #pragma unroll
                for (int oo = 0; oo < 2; oo++) {
                    int o = o0y + oo;
                    float4 xq0 = *(const float4*)(xc + o * SD + seg * 8);
                    float4 xq1 = *(const float4*)(xc + o * SD + seg * 8 + 4);
                    float av = al[o], cf = Cv[o];
                    const __half* Wp = W1h + ((size_t)o << 12) + (seg << 3);
                    #pragma unroll 4
                    for (int db_ = 0; db_ < 64; db_ += 4) {
                        int d = db_ + rg;
                        uint4 g = *(const uint4*)(Wp + (d << 6));
                        float2 t0 = __half22float2(*(__half2*)&g.x);
                        float2 t1 = __half22float2(*(__half2*)&g.y);
                        float2 t2 = __half22float2(*(__half2*)&g.z);
                        float2 t3 = __half22float2(*(__half2*)&g.w);
                        float p = t0.x * xq0.x + t0.y * xq0.y + t1.x * xq0.z + t1.y * xq0.w
                                + t2.x * xq1.x + t2.y * xq1.y + t3.x * xq1.z + t3.y * xq1.w;
                        p += __shfl_xor_sync(0xffffffffu, p, 1);
                        p += __shfl_xor_sync(0xffffffffu, p, 2);
                        p += __shfl_xor_sync(0xffffffffu, p, 4);
                        if (seg == 0) {
                            float v = av * (p + cf * bias[o * 64 + d]);
                            xs[d * SD + o] = v;     // x_next[c=d][i=o]
                            xt[o * SD + d] = v;     // xt_next[i=o][c=d]
                        }
                    }
                }
            }
            __syncthreads();
        } else {
            // ---- final: v[o][d] via fp32 W2 (16-lane rows) -> gmem ----
            if (o0y < O) {
                const int s16 = lane & 15, rg2 = lane >> 4;
                #pragma unroll
                for (int oo = 0; oo < 2; oo++) {
                    int o = o0y + oo;
                    float4 xq = *(const float4*)(xc + o * SD + s16 * 4);
                    float av = al[o], cf = Cv[o];
                    const float* Wp = W2f + (size_t)(o * 64) * 64 + s16 * 4;
                    #pragma unroll 4
                    for (int db_ = 0; db_ < 64; db_ += 2) {
                        int d = db_ + rg2;
                        float4 wv = *(const float4*)(Wp + (d << 6));
                        float p = wv.x * xq.x + wv.y * xq.y + wv.z * xq.z + wv.w * xq.w;
                        p += __shfl_xor_sync(0xffffffffu, p, 1);
                        p += __shfl_xor_sync(0xffffffffu, p, 2);
                        p += __shfl_xor_sync(0xffffffffu, p, 4);
                        p += __shfl_xor_sync(0xffffffffu, p, 8);
                        if (s16 == 0)
                            outp[o * 64 + d] = av * (p + cf * bias[o * 64 + d]);
                    }
                }
            }
            __syncthreads();
        }
    }
}

// ---------------------------------------------------------------------------
// Main fused kernel: conv3x3 + relu + channel squash, then 3+1 capsule layers.
// ---------------------------------------------------------------------------
__global__ void __launch_bounds__(1024, 1)
caps_kernel(const float* __restrict__ gx,  const float* __restrict__ gWb, const float* __restrict__ gbb,
            const float* __restrict__ W1,  const float* __restrict__ b1,
            const float* __restrict__ W2,  const float* __restrict__ b2,
            const float* __restrict__ b_basic, const float* __restrict__ b_cls,
            float* __restrict__ out)
{
    extern __shared__ float sm[];
    int tid = threadIdx.x;
    int b = blockIdx.x;
    float* xs    = sm + XS_OFF;
    float* xt    = sm + XT_OFF;
    float* cvout = sm + XC_OFF;      // conv output staging
    float* wbs   = sm + WBS_OFF;
    float* fac   = sm + AUX_OFF + 384;
    float* PS    = sm + PS_OFF;

    // load x[b]: xs[c][i]
    const float* xb = gx + (size_t)b * 4096;
    {
        int c = tid >> 4, q = tid & 15;
        float4 v = ((const float4*)(xb + c * 64))[q];
        xs[c * SD + q * 4 + 0] = v.x;
        xs[c * SD + q * 4 + 1] = v.y;
        xs[c * SD + q * 4 + 2] = v.z;
        xs[c * SD + q * 4 + 3] = v.w;
    }
    // conv weights [64 co][576] at stride 577
    for (int p = tid; p < 36864; p += 1024) {
        int co = p / 576, r = p - co * 576;
        wbs[co * 577 + r] = gWb[p];
    }
    __syncthreads();

    // conv 3x3 SAME. Warp -> position group; lane -> co (coalesced weights).
    {
        int wA = tid >> 5, lane = tid & 31;
        int pg = wA >> 1;
        int y0 = pg >> 1, h = pg & 1;
        int co = (wA & 1) * 32 + lane;
        float acc0, acc1, acc2, acc3;
        {
            float bval = gbb[co];
            acc0 = acc1 = acc2 = acc3 = bval;
        }
        const float* wr = wbs + co * 577;
        for (int ci = 0; ci < 64; ci++) {
            const float* xrow = xs + ci * SD;
            const float* wci = wr + ci * 9;
            float w0 = wci[0], w1 = wci[1], w2 = wci[2];
            float w3 = wci[3], w4 = wci[4], w5 = wci[5];
            float w6 = wci[6], w7 = wci[7], w8 = wci[8];
            #pragma unroll
            for (int ky = 0; ky < 3; ky++) {
                int yy = y0 + ky - 1;
                if (yy >= 0 && yy <= 7) {
                    float4 m = *(const float4*)(xrow + yy * 8 + h * 4);   // bcast
                    float rp0 = h ? xrow[yy * 8 + 3] : 0.f;
                    float rp5 = h ? 0.f : xrow[yy * 8 + 4];
                    float ta = (ky == 0) ? w0 : (ky == 1) ? w3 : w6;
                    float tb = (ky == 0) ? w1 : (ky == 1) ? w4 : w7;
                    float tc = (ky == 0) ? w2 : (ky == 1) ? w5 : w8;
                    acc0 += ta * rp0 + tb * m.x + tc * m.y;
                    acc1 += ta * m.x + tb * m.y + tc * m.z;
                    acc2 += ta * m.y + tb * m.z + tc * m.w;
                    acc3 += ta * m.z + tb * m.w + tc * rp5;
                }
            }
        }
        int base = y0 * 8 + h * 4;
        cvout[co * SD + base + 0] = fmaxf(acc0, 0.f);
        cvout[co * SD + base + 1] = fmaxf(acc1, 0.f);
        cvout[co * SD + base + 2] = fmaxf(acc2, 0.f);
        cvout[co * SD + base + 3] = fmaxf(acc3, 0.f);
    }
    __syncthreads();

    // channel squash per spatial position
    {
        int i = tid & 63, g = tid >> 6;
        float n2 = 0.f;
        #pragma unroll
        for (int k = 0; k < 4; k++) {
            float hv = cvout[(4 * g + k) * SD + i];
            n2 += hv * hv;
        }
        PS[g * SDS + i] = n2;
    }
    __syncthreads();
    if (tid < 64) {
        float n2 = 0.f;
        for (int g = 0; g < 16; g++) n2 += PS[g * SDS + tid];
        fac[tid] = (n2 / (1.f + n2)) * rsqrtf(n2 + 1e-8f);
    }
    __syncthreads();
    {
        int i = tid & 63, g = tid >> 6;
        float f = fac[i];
        #pragma unroll
        for (int k = 0; k < 4; k++) {
            int c = 4 * g + k;
            float v = cvout[c * SD + i] * f;
            xs[c * SD + i] = v;       // different region than cvout: safe
            xt[i * SD + c] = v;
        }
    }
    __syncthreads();

    for (int L = 0; L < 3; L++)
        cap_layer(64, false, nullptr, g_W1h, b1, g_G1h, g_BW1, g_Bn1,
                  b_basic + (size_t)(L * 128 + b) * 4096, nullptr, sm, tid);
    cap_layer(10, true, W2, nullptr, b2, g_G2h, g_BW2, g_Bn2,
              b_cls + (size_t)b * 640, out + (size_t)b * 640, sm, tid);
}

// ---------------------------------------------------------------------------
static const float* pick(void* const* d_in, const int* in_sizes, int n_in, int sz) {
    for (int i = 0; i < n_in; i++)
        if (in_sizes[i] == sz) return (const float*)d_in[i];
    return nullptr;
}

extern "C" void kernel_launch(void* const* d_in, const int* in_sizes, int n_in,
                              void* d_out, int out_size)
{
    const float* x       = pick(d_in, in_sizes, n_in, 128 * 64 * 64);
    const float* Wb      = pick(d_in, in_sizes, n_in, 64 * 64 * 9);
    const float* bb      = pick(d_in, in_sizes, n_in, 64);
    const float* W1      = pick(d_in, in_sizes, n_in, 4096 * 64);
    const float* b1      = pick(d_in, in_sizes, n_in, 4096);
    const float* W2      = pick(d_in, in_sizes, n_in, 640 * 64);
    const float* b2      = pick(d_in, in_sizes, n_in, 640);
    const float* b_basic = pick(d_in, in_sizes, n_in, 3 * 128 * 64 * 64);
    const float* b_cls   = pick(d_in, in_sizes, n_in, 128 * 10 * 64);
    float* out = (float*)d_out;

    cudaFuncSetAttribute(caps_kernel, cudaFuncAttributeMaxDynamicSharedMemorySize, SMEM_BYTES);
    gram_kernel<<<74, 256>>>(W1, b1, W2, b2);
    caps_kernel<<<128, 1024, SMEM_BYTES>>>(x, Wb, bb, W1, b1, W2, b2, b_basic, b_cls, out);
}

// round 7
// speedup vs baseline: 2.3935x; 1.0145x over previous
#include <cuda_runtime.h>
#include <cuda_fp16.h>
#include <math.h>

// ---------------------------------------------------------------------------
// CapsNet forward, fully fused, 1 CTA / batch element, 1024 threads.
// Gram trick: routing never materializes pred.
//   xc[o,c]=sum_i c[o,i]x[c,i];  y[o]=G[o]xc[o]+C*BW[o]  (G=W W^T, fp16)
//   |s|^2=xc.y+C*sB; v=alpha*s;  db[o,i]=alpha*(sum_c y[o,c]x[c,i]+sB)
// E=exp(b) maintained directly (no logits); exp fused into db epilogue.
// R6: ALL 32 warps active in every major phase (4o x 32c GEMM tiles),
// redundant per-thread ginv (no serial tid<64 phases), Cv partials consumed
// directly by y/W passes. 4 barriers per routing iteration.
// ---------------------------------------------------------------------------

#define SD  68                   // row stride (floats), float4-capable
#define SDS 66                   // staging stride

#define XS_OFF   0               // xs[c][i]   64x68
#define XT_OFF   4352            // xt[i][c]   64x68
#define XC_OFF   8704            // xc[o][c]   64x68 (conv-out staging too)
#define CT_OFF   13056           // ct[i][o]   64x68: E, then normalized c
#define YT_OFF   17408           // yt[c][o]   64x68
#define AUX_OFF  21760           // al[64]|sB[64]|CvP[128]|fac[64]
#define PS_OFF   22272           // 16x66 partial sums
#define WBS_OFF  13056           // conv weights overlay 64x577
#define SMEM_FLOATS 49984
#define SMEM_BYTES (SMEM_FLOATS * 4)

__device__ __align__(16) __half g_G1h[64 * 64 * 64];
__device__ __align__(16) __half g_G2h[10 * 64 * 64];
__device__ __align__(16) __half g_W1h[64 * 64 * 64];
__device__ float g_BW1[64 * 64];
__device__ float g_Bn1[64];
__device__ float g_BW2[10 * 64];
__device__ float g_Bn2[16];

// ---------------------------------------------------------------------------
__global__ void gram_kernel(const float* __restrict__ W1, const float* __restrict__ b1,
                            const float* __restrict__ W2, const float* __restrict__ b2)
{
    __shared__ float ws[64 * SD];
    __shared__ float bsv[64];
    int blk = blockIdx.x;
    const float* W;
    const float* bias;
    __half* G; float* BW; float* Bn;
    int o;
    if (blk < 64) { o = blk;      W = W1; bias = b1; G = g_G1h + o * 4096; BW = g_BW1 + o * 64; Bn = g_Bn1 + o; }
    else          { o = blk - 64; W = W2; bias = b2; G = g_G2h + o * 4096; BW = g_BW2 + o * 64; Bn = g_Bn2 + o; }
    int tid = threadIdx.x;  // 256

    for (int p = tid; p < 64 * 16; p += 256) {
        int d = p >> 4, q = p & 15;
        float4 v = ((const float4*)(W + (o * 64 + d) * 64))[q];
        ws[d * SD + q * 4 + 0] = v.x;
        ws[d * SD + q * 4 + 1] = v.y;
        ws[d * SD + q * 4 + 2] = v.z;
        ws[d * SD + q * 4 + 3] = v.w;
    }
    if (tid < 64) bsv[tid] = bias[o * 64 + tid];
    __syncthreads();

    for (int p = tid; p < 64 * 16; p += 256) {
        int c = p >> 4, c4 = (p & 15) * 4;
        float a0 = 0.f, a1 = 0.f, a2 = 0.f, a3 = 0.f;
        #pragma unroll 4
        for (int d = 0; d < 64; d++) {
            float wc = ws[d * SD + c];
            a0 += wc * ws[d * SD + c4 + 0];
            a1 += wc * ws[d * SD + c4 + 1];
            a2 += wc * ws[d * SD + c4 + 2];
            a3 += wc * ws[d * SD + c4 + 3];
        }
        G[c * 64 + c4 + 0] = __float2half_rn(a0);
        G[c * 64 + c4 + 1] = __float2half_rn(a1);
        G[c * 64 + c4 + 2] = __float2half_rn(a2);
        G[c * 64 + c4 + 3] = __float2half_rn(a3);
    }
    if (blk < 64) {
        for (int p = tid; p < 2048; p += 256) {
            int d = p >> 5, c2 = (p & 31) * 2;
            __half2 hv = __floats2half2_rn(ws[d * SD + c2], ws[d * SD + c2 + 1]);
            *((__half2*)(g_W1h + ((size_t)o << 12) + d * 64 + c2)) = hv;
        }
    }
    if (tid < 64) {
        float acc = 0.f;
        for (int d = 0; d < 64; d++) acc += bsv[d] * ws[d * SD + tid];
        BW[tid] = acc;
    }
    if (tid == 64) {
        float acc = 0.f;
        for (int d = 0; d < 64; d++) acc += bsv[d] * bsv[d];
        *Bn = acc;
    }
}

// ---------------------------------------------------------------------------
// One capsule layer, 3 routing iterations. O = 64 or 10.
// ---------------------------------------------------------------------------
__device__ __forceinline__ void cap_layer(
    int O, bool is_final,
    const float* __restrict__ W2f, const __half* __restrict__ W1h,
    const float* __restrict__ bias,
    const __half* __restrict__ Gh, const float* __restrict__ BW, const float* __restrict__ Bn,
    const float* __restrict__ b0, float* __restrict__ outp,
    float* sm, int tid)
{
    float* xs  = sm + XS_OFF;
    float* xt  = sm + XT_OFF;
    float* xc  = sm + XC_OFF;
    float* ct  = sm + CT_OFF;
    float* yt  = sm + YT_OFF;
    float* al  = sm + AUX_OFF;
    float* sB  = sm + AUX_OFF + 64;
    float* CvP = sm + AUX_OFF + 128;
    float* PS  = sm + PS_OFF;

    const int w = tid >> 5, lane = tid & 31;
    const int ii = tid & 63, gg = tid >> 6;        // (i, 4-o group)
    const int ngrp = (O + 3) >> 2;                 // PS rows / o-groups
    const int o0t  = (w >> 1) << 2;                // GEMM tile: 4 o per warp pair
    const int hb2  = (w & 1) << 5;                 // 32-wide half (c or i)
    const int half = (w & 1);
    const int o0y  = w << 1;                       // y/W pass: 2 o per warp

    // ---- E0 = exp(b0), with per-(group,i) partial sums ----
    if (gg < ngrp) {
        int ob = gg << 2;
        float e0 = __expf(b0[ob * 64 + ii]);
        float e1 = (ob + 1 < O) ? __expf(b0[(ob + 1) * 64 + ii]) : 0.f;
        float e2 = (ob + 2 < O) ? __expf(b0[(ob + 2) * 64 + ii]) : 0.f;
        float e3 = (ob + 3 < O) ? __expf(b0[(ob + 3) * 64 + ii]) : 0.f;
        *(float4*)(ct + ii * SD + ob) = make_float4(e0, e1, e2, e3);
        PS[gg * SDS + ii] = e0 + e1 + e2 + e3;
    }
    __syncthreads();

    for (int it = 0; it < 3; it++) {
        // ---- phase A: ginv (redundant per thread) + normalize + Cv partials --
        {
            float s = 0.f;
            for (int g = 0; g < ngrp; g++) s += PS[g * SDS + ii];
            float gi = 1.f / s;
            if (gg < ngrp) {
                float4 e4 = *(float4*)(ct + ii * SD + (gg << 2));
                e4.x *= gi; e4.y *= gi; e4.z *= gi; e4.w *= gi;
                *(float4*)(ct + ii * SD + (gg << 2)) = e4;
                float s0 = e4.x, s1 = e4.y, s2 = e4.z, s3 = e4.w;
                #pragma unroll
                for (int k = 16; k; k >>= 1) {
                    s0 += __shfl_xor_sync(0xffffffffu, s0, k);
                    s1 += __shfl_xor_sync(0xffffffffu, s1, k);
                    s2 += __shfl_xor_sync(0xffffffffu, s2, k);
                    s3 += __shfl_xor_sync(0xffffffffu, s3, k);
                }
                if (lane == 0) {
                    float* dst = CvP + half * 64 + (gg << 2);
                    dst[0] = s0; dst[1] = s1; dst[2] = s2; dst[3] = s3;
                }
            }
        }
        __syncthreads();

        // ---- xc[o][c] = sum_i c[o,i]*xt[i][c]; 4o x 32c tile, ALL warps ----
        if (o0t < O) {
            float a0 = 0.f, a1 = 0.f, a2 = 0.f, a3 = 0.f;
            #pragma unroll 8
            for (int i = 0; i < 64; i++) {
                float4 cv = *(const float4*)(ct + i * SD + o0t);   // bcast
                float xv = xt[i * SD + hb2 + lane];                // coalesced
                a0 += cv.x * xv; a1 += cv.y * xv;
                a2 += cv.z * xv; a3 += cv.w * xv;
            }
            xc[o0t * SD + hb2 + lane] = a0;
            if (o0t + 1 < O) xc[(o0t + 1) * SD + hb2 + lane] = a1;
            if (o0t + 2 < O) xc[(o0t + 2) * SD + hb2 + lane] = a2;
            if (o0t + 3 < O) xc[(o0t + 3) * SD + hb2 + lane] = a3;
        }
        __syncthreads();

        // ---- y[o] = G[o] xc[o] + C*BW[o]; cooperative coalesced G rows ----
        if (o0y < O) {
            const int seg = lane & 7, rgrp = lane >> 3;
            #pragma unroll
            for (int oo = 0; oo < 2; oo++) {
                int o = o0y + oo;
                const __half* Gp = Gh + ((size_t)o << 12) + (seg << 3);
                float4 xq0 = *(const float4*)(xc + o * SD + seg * 8);
                float4 xq1 = *(const float4*)(xc + o * SD + seg * 8 + 4);
                float cf = CvP[o] + CvP[64 + o];
                #pragma unroll 8
                for (int rb = 0; rb < 64; rb += 4) {
                    int r = rb + rgrp;
                    uint4 g = *(const uint4*)(Gp + (r << 6));
                    float2 t0 = __half22float2(*(__half2*)&g.x);
                    float2 t1 = __half22float2(*(__half2*)&g.y);
                    float2 t2 = __half22float2(*(__half2*)&g.z);
                    float2 t3 = __half22float2(*(__half2*)&g.w);
                    float p = t0.x * xq0.x + t0.y * xq0.y + t1.x * xq0.z + t1.y * xq0.w
                            + t2.x * xq1.x + t2.y * xq1.y + t3.x * xq1.z + t3.y * xq1.w;
                    p += __shfl_xor_sync(0xffffffffu, p, 1);
                    p += __shfl_xor_sync(0xffffffffu, p, 2);
                    p += __shfl_xor_sync(0xffffffffu, p, 4);
                    if (seg == 0)
                        yt[r * SD + o] = cf * BW[o * 64 + r] + p;
                }
            }
            __syncwarp();
            // ---- |s|^2, sB, alpha per o ----
            #pragma unroll
            for (int oo = 0; oo < 2; oo++) {
                int o = o0y + oo;
                float y0 = yt[lane * SD + o],  y1 = yt[(lane + 32) * SD + o];
                float x0 = xc[o * SD + lane],  x1 = xc[o * SD + lane + 32];
                float b0w = BW[o * 64 + lane], b1w = BW[o * 64 + lane + 32];
                float nn = y0 * x0 + y1 * x1;
                float sb = b0w * x0 + b1w * x1;
                #pragma unroll
                for (int k = 16; k; k >>= 1) {
                    nn += __shfl_xor_sync(0xffffffffu, nn, k);
                    sb += __shfl_xor_sync(0xffffffffu, sb, k);
                }
                if (lane == 0) {
                    float cf = CvP[o] + CvP[64 + o];
                    sb += cf * Bn[o];
                    nn += cf * sb;
                    sB[o] = sb;
                    al[o] = (nn / (1.f + nn)) * rsqrtf(nn + 1e-8f);
                }
            }
        }
        __syncthreads();

        if (it < 2) {
            // ---- db GEMM + fused E update: E = c*exp(db); 4o x 32i, ALL warps --
            if (o0t < O) {
                int i = hb2 + lane;
                float a0 = 0.f, a1 = 0.f, a2 = 0.f, a3 = 0.f;
                #pragma unroll 8
                for (int c = 0; c < 64; c++) {
                    float4 yv = *(const float4*)(yt + c * SD + o0t);   // bcast
                    float xv = xs[c * SD + i];                         // coalesced
                    a0 += yv.x * xv; a1 += yv.y * xv;
                    a2 += yv.z * xv; a3 += yv.w * xv;
                }
                float4 cin = *(float4*)(ct + i * SD + o0t);
                float e0 = 0.f, e1 = 0.f, e2 = 0.f, e3 = 0.f;
                e0 = cin.x * __expf(al[o0t] * (a0 + sB[o0t]));
                if (o0t + 1 < O) e1 = cin.y * __expf(al[o0t + 1] * (a1 + sB[o0t + 1]));
                if (o0t + 2 < O) e2 = cin.z * __expf(al[o0t + 2] * (a2 + sB[o0t + 2]));
                if (o0t + 3 < O) e3 = cin.w * __expf(al[o0t + 3] * (a3 + sB[o0t + 3]));
                *(float4*)(ct + i * SD + o0t) = make_float4(e0, e1, e2, e3);
                PS[(o0t >> 2) * SDS + i] = e0 + e1 + e2 + e3;
            }
            __syncthreads();
        } else if (!is_final) {
            // ---- v[o][d] = alpha*((W1 xc)[o,d] + C*B[o,d]); fp16 W rows ----
            if (o0y < O) {
                const int seg = lane & 7, rg = lane >> 3;
                #pragma unroll
                for (int oo = 0; oo < 2; oo++) {
                    int o = o0y + oo;
                    float4 xq0 = *(const float4*)(xc + o * SD + seg * 8);
                    float4 xq1 = *(const float4*)(xc + o * SD + seg * 8 + 4);
                    float av = al[o];
                    float cf = CvP[o] + CvP[64 + o];
                    const __half* Wp = W1h + ((size_t)o << 12) + (seg << 3);
                    #pragma unroll 8
                    for (int db_ = 0; db_ < 64; db_ += 4) {
                        int d = db_ + rg;
                        uint4 g = *(const uint4*)(Wp + (d << 6));
                        float2 t0 = __half22float2(*(__half2*)&g.x);
                        float2 t1 = __half22float2(*(__half2*)&g.y);
                        float2 t2 = __half22float2(*(__half2*)&g.z);
                        float2 t3 = __half22float2(*(__half2*)&g.w);
                        float p = t0.x * xq0.x + t0.y * xq0.y + t1.x * xq0.z + t1.y * xq0.w
                                + t2.x * xq1.x + t2.y * xq1.y + t3.x * xq1.z + t3.y * xq1.w;
                        p += __shfl_xor_sync(0xffffffffu, p, 1);
                        p += __shfl_xor_sync(0xffffffffu, p, 2);
                        p += __shfl_xor_sync(0xffffffffu, p, 4);
                        if (seg == 0) {
                            float v = av * (p + cf * bias[o * 64 + d]);
                            xs[d * SD + o] = v;     // x_next[c=d][i=o]
                            xt[o * SD + d] = v;     // xt_next[i=o][c=d]
                        }
                    }
                }
            }
            __syncthreads();
        } else {
            // ---- final: v[o][d] via fp32 W2 (16-lane rows) -> gmem ----
            if (o0y < O) {
                const int s16 = lane & 15, rg2 = lane >> 4;
                #pragma unroll
                for (int oo = 0; oo < 2; oo++) {
                    int o = o0y + oo;
                    float4 xq = *(const float4*)(xc + o * SD + s16 * 4);
                    float av = al[o];
                    float cf = CvP[o] + CvP[64 + o];
                    const float* Wp = W2f + (size_t)(o * 64) * 64 + s16 * 4;
                    #pragma unroll 8
                    for (int db_ = 0; db_ < 64; db_ += 2) {
                        int d = db_ + rg2;
                        float4 wv = *(const float4*)(Wp + (d << 6));
                        float p = wv.x * xq.x + wv.y * xq.y + wv.z * xq.z + wv.w * xq.w;
                        p += __shfl_xor_sync(0xffffffffu, p, 1);
                        p += __shfl_xor_sync(0xffffffffu, p, 2);
                        p += __shfl_xor_sync(0xffffffffu, p, 4);
                        p += __shfl_xor_sync(0xffffffffu, p, 8);
                        if (s16 == 0)
                            outp[o * 64 + d] = av * (p + cf * bias[o * 64 + d]);
                    }
                }
            }
            __syncthreads();
        }
    }
}

// ---------------------------------------------------------------------------
// Main fused kernel: conv3x3 + relu + channel squash, then 3+1 capsule layers.
// ---------------------------------------------------------------------------
__global__ void __launch_bounds__(1024, 1)
caps_kernel(const float* __restrict__ gx,  const float* __restrict__ gWb, const float* __restrict__ gbb,
            const float* __restrict__ W1,  const float* __restrict__ b1,
            const float* __restrict__ W2,  const float* __restrict__ b2,
            const float* __restrict__ b_basic, const float* __restrict__ b_cls,
            float* __restrict__ out)
{
    extern __shared__ float sm[];
    int tid = threadIdx.x;
    int b = blockIdx.x;
    float* xs    = sm + XS_OFF;
    float* xt    = sm + XT_OFF;
    float* cvout = sm + XC_OFF;      // conv output staging
    float* wbs   = sm + WBS_OFF;
    float* fac   = sm + AUX_OFF + 256;
    float* PS    = sm + PS_OFF;

    // load x[b]: xs[c][i]
    const float* xb = gx + (size_t)b * 4096;
    {
        int c = tid >> 4, q = tid & 15;
        float4 v = ((const float4*)(xb + c * 64))[q];
        xs[c * SD + q * 4 + 0] = v.x;
        xs[c * SD + q * 4 + 1] = v.y;
        xs[c * SD + q * 4 + 2] = v.z;
        xs[c * SD + q * 4 + 3] = v.w;
    }
    // conv weights [64 co][576] at stride 577
    for (int p = tid; p < 36864; p += 1024) {
        int co = p / 576, r = p - co * 576;
        wbs[co * 577 + r] = gWb[p];
    }
    __syncthreads();

    // conv 3x3 SAME. Warp -> position group; lane -> co (coalesced weights).
    {
        int wA = tid >> 5, lane = tid & 31;
        int pg = wA >> 1;
        int y0 = pg >> 1, h = pg & 1;
        int co = (wA & 1) * 32 + lane;
        float acc0, acc1, acc2, acc3;
        {
            float bval = gbb[co];
            acc0 = acc1 = acc2 = acc3 = bval;
        }
        const float* wr = wbs + co * 577;
        for (int ci = 0; ci < 64; ci++) {
            const float* xrow = xs + ci * SD;
            const float* wci = wr + ci * 9;
            float w0 = wci[0], w1 = wci[1], w2 = wci[2];
            float w3 = wci[3], w4 = wci[4], w5 = wci[5];
            float w6 = wci[6], w7 = wci[7], w8 = wci[8];
            #pragma unroll
            for (int ky = 0; ky < 3; ky++) {
                int yy = y0 + ky - 1;
                if (yy >= 0 && yy <= 7) {
                    float4 m = *(const float4*)(xrow + yy * 8 + h * 4);   // bcast
                    float rp0 = h ? xrow[yy * 8 + 3] : 0.f;
                    float rp5 = h ? 0.f : xrow[yy * 8 + 4];
                    float ta = (ky == 0) ? w0 : (ky == 1) ? w3 : w6;
                    float tb = (ky == 0) ? w1 : (ky == 1) ? w4 : w7;
                    float tc = (ky == 0) ? w2 : (ky == 1) ? w5 : w8;
                    acc0 += ta * rp0 + tb * m.x + tc * m.y;
                    acc1 += ta * m.x + tb * m.y + tc * m.z;
                    acc2 += ta * m.y + tb * m.z + tc * m.w;
                    acc3 += ta * m.z + tb * m.w + tc * rp5;
                }
            }
        }
        int base = y0 * 8 + h * 4;
        cvout[co * SD + base + 0] = fmaxf(acc0, 0.f);
        cvout[co * SD + base + 1] = fmaxf(acc1, 0.f);
        cvout[co * SD + base + 2] = fmaxf(acc2, 0.f);
        cvout[co * SD + base + 3] = fmaxf(acc3, 0.f);
    }
    __syncthreads();

    // channel squash per spatial position
    {
        int i = tid & 63, g = tid >> 6;
        float n2 = 0.f;
        #pragma unroll
        for (int k = 0; k < 4; k++) {
            float hv = cvout[(4 * g + k) * SD + i];
            n2 += hv * hv;
        }
        PS[g * SDS + i] = n2;
    }
    __syncthreads();
    if (tid < 64) {
        float n2 = 0.f;
        for (int g = 0; g < 16; g++) n2 += PS[g * SDS + tid];
        fac[tid] = (n2 / (1.f + n2)) * rsqrtf(n2 + 1e-8f);
    }
    __syncthreads();
    {
        int i = tid & 63, g = tid >> 6;
        float f = fac[i];
        #pragma unroll
        for (int k = 0; k < 4; k++) {
            int c = 4 * g + k;
            float v = cvout[c * SD + i] * f;
            xs[c * SD + i] = v;       // different region than cvout: safe
            xt[i * SD + c] = v;
        }
    }
    __syncthreads();

    for (int L = 0; L < 3; L++)
        cap_layer(64, false, nullptr, g_W1h, b1, g_G1h, g_BW1, g_Bn1,
                  b_basic + (size_t)(L * 128 + b) * 4096, nullptr, sm, tid);
    cap_layer(10, true, W2, nullptr, b2, g_G2h, g_BW2, g_Bn2,
              b_cls + (size_t)b * 640, out + (size_t)b * 640, sm, tid);
}

// ---------------------------------------------------------------------------
static const float* pick(void* const* d_in, const int* in_sizes, int n_in, int sz) {
    for (int i = 0; i < n_in; i++)
        if (in_sizes[i] == sz) return (const float*)d_in[i];
    return nullptr;
}

extern "C" void kernel_launch(void* const* d_in, const int* in_sizes, int n_in,
                              void* d_out, int out_size)
{
    const float* x       = pick(d_in, in_sizes, n_in, 128 * 64 * 64);
    const float* Wb      = pick(d_in, in_sizes, n_in, 64 * 64 * 9);
    const float* bb      = pick(d_in, in_sizes, n_in, 64);
    const float* W1      = pick(d_in, in_sizes, n_in, 4096 * 64);
    const float* b1      = pick(d_in, in_sizes, n_in, 4096);
    const float* W2      = pick(d_in, in_sizes, n_in, 640 * 64);
    const float* b2      = pick(d_in, in_sizes, n_in, 640);
    const float* b_basic = pick(d_in, in_sizes, n_in, 3 * 128 * 64 * 64);
    const float* b_cls   = pick(d_in, in_sizes, n_in, 128 * 10 * 64);
    float* out = (float*)d_out;

    cudaFuncSetAttribute(caps_kernel, cudaFuncAttributeMaxDynamicSharedMemorySize, SMEM_BYTES);
    gram_kernel<<<74, 256>>>(W1, b1, W2, b2);
    caps_kernel<<<128, 1024, SMEM_BYTES>>>(x, Wb, bb, W1, b1, W2, b2, b_basic, b_cls, out);
}